// round 9
// baseline (speedup 1.0000x reference)
#include <cuda_runtime.h>
#include <cuda_bf16.h>
#include <math.h>

// Problem constants
#define Bn   2
#define Nn   2048
#define Hn   8
#define DHn  32
#define En   65536
#define DINn 256
#define On   256            // H*DH
#define INVSCALE 0.17677669529663687f   // 1/sqrt(32)
#define LOGCLIP  -13.815510557964274f   // log(1e-6)

#define KT 64               // keys per tile
#define NTILES (Nn / KT)    // 32
#define KPAD 36             // padded row (floats), 16B aligned
#define QROWS 4             // q rows per warp
#define CTAQ  32            // q rows per CTA (8 warps * 4)

typedef unsigned long long ull;

// -------- f32x2 packed math (sm_103a; ptxas won't auto-fuse) --------
__device__ __forceinline__ ull fma2(ull a, ull b, ull c) {
    ull d; asm("fma.rn.f32x2 %0, %1, %2, %3;" : "=l"(d) : "l"(a), "l"(b), "l"(c)); return d;
}
__device__ __forceinline__ ull mul2(ull a, ull b) {
    ull d; asm("mul.rn.f32x2 %0, %1, %2;" : "=l"(d) : "l"(a), "l"(b)); return d;
}
__device__ __forceinline__ ull add2(ull a, ull b) {
    ull d; asm("add.rn.f32x2 %0, %1, %2;" : "=l"(d) : "l"(a), "l"(b)); return d;
}
__device__ __forceinline__ ull dup2(float x) {
    ull r; asm("mov.b64 %0, {%1, %1};" : "=l"(r) : "f"(x)); return r;
}
__device__ __forceinline__ float hsum2(ull v) {
    float a, b; asm("mov.b64 {%0, %1}, %2;" : "=f"(a), "=f"(b) : "l"(v)); return a + b;
}
__device__ __forceinline__ void unpack2(ull v, float& a, float& b) {
    asm("mov.b64 {%0, %1}, %2;" : "=f"(a), "=f"(b) : "l"(v));
}

// -------- static device scratch (no allocations allowed) --------
// g_eid: zero-initialized at module load; edge_kernel rewrites the SAME slots
// with the SAME values on every launch (edge_index is a fixed input with
// unique (u,v) pairs) -> no per-launch clearing needed.
__device__ float g_Q[Bn * Hn * Nn * DHn];
__device__ float g_K[Bn * Hn * Nn * DHn];
__device__ float g_V[Bn * Hn * Nn * DHn];
__device__ float g_ea[Bn * Hn * En];
__device__ int   g_eid[(size_t)Bn * Nn * Nn];

// -------- cp.async helpers --------
#define CP_ASYNC16(smem_u32, gptr) \
    asm volatile("cp.async.cg.shared.global [%0], [%1], 16;" :: "r"(smem_u32), "l"(gptr))
#define CP_COMMIT() asm volatile("cp.async.commit_group;")
#define CP_WAIT1()  asm volatile("cp.async.wait_group 1;")
#define CP_WAIT0()  asm volatile("cp.async.wait_group 0;")

// ================= QKV projection =================
__global__ __launch_bounds__(256) void qkv_kernel(
    const float* __restrict__ x, const float* __restrict__ w,
    const float* __restrict__ bias)
{
    __shared__ float As[16][68];
    __shared__ float Bs[16][68];
    const int tid = threadIdx.x;
    const int tx = tid & 15, ty = tid >> 4;
    const int row0 = blockIdx.y * 64;
    const int col0 = blockIdx.x * 64;

    float c[4][4] = {};
    for (int k0 = 0; k0 < DINn; k0 += 16) {
        {
            int kk = tid & 15, mb = tid >> 4;
            #pragma unroll
            for (int j = 0; j < 4; ++j) {
                int m = mb + j * 16;
                As[kk][m] = x[(size_t)(row0 + m) * DINn + k0 + kk];
            }
        }
        {
            int cc = tid & 63, kb = tid >> 6;
            #pragma unroll
            for (int j = 0; j < 4; ++j) {
                int kk = kb + j * 4;
                Bs[kk][cc] = w[(size_t)(k0 + kk) * 768 + col0 + cc];
            }
        }
        __syncthreads();
        #pragma unroll
        for (int kk = 0; kk < 16; ++kk) {
            float a[4], bb[4];
            #pragma unroll
            for (int i = 0; i < 4; ++i) a[i] = As[kk][ty * 4 + i];
            #pragma unroll
            for (int j = 0; j < 4; ++j) bb[j] = Bs[kk][tx * 4 + j];
            #pragma unroll
            for (int i = 0; i < 4; ++i)
                #pragma unroll
                for (int j = 0; j < 4; ++j)
                    c[i][j] = fmaf(a[i], bb[j], c[i][j]);
        }
        __syncthreads();
    }
    #pragma unroll
    for (int i = 0; i < 4; ++i) {
        int row = row0 + ty * 4 + i;
        int bb_ = row >> 11, n = row & (Nn - 1);
        #pragma unroll
        for (int j = 0; j < 4; ++j) {
            int col = col0 + tx * 4 + j;
            float v = c[i][j] + __ldg(bias + col);
            int s = col >> 8, hh = (col >> 5) & 7, d = col & 31;
            float* dst = (s == 0) ? g_Q : (s == 1) ? g_K : g_V;
            dst[(((size_t)(bb_ * Hn + hh)) * Nn + n) * DHn + d] = v;
        }
    }
}

// ================= edge FFN + scatter =================
__global__ __launch_bounds__(256) void edge_kernel(
    const float* __restrict__ edge_attr,
    const float* __restrict__ e_w1, const float* __restrict__ e_b1,
    const float* __restrict__ e_w2, const float* __restrict__ e_b2,
    const int*   __restrict__ edge_index)
{
    __shared__ float w1s[64], w2s[64], b1s[8], b2s[8];
    int tid = threadIdx.x;
    if (tid < 64) { w1s[tid] = e_w1[tid]; w2s[tid] = e_w2[tid]; }
    if (tid < 8)  { b1s[tid] = e_b1[tid]; b2s[tid] = e_b2[tid]; }
    __syncthreads();

    int gid = blockIdx.x * 256 + tid;
    int b = gid >> 16;
    int e = gid & (En - 1);

    float cur[8];
    const float* ap = edge_attr + ((size_t)b * En + e) * Hn;
    #pragma unroll
    for (int i = 0; i < 8; ++i) cur[i] = ap[i];

    #pragma unroll
    for (int pass = 0; pass < 2; ++pass) {
        float t1[8], t2[8];
        #pragma unroll
        for (int j = 0; j < 8; ++j) {
            float s = b1s[j];
            #pragma unroll
            for (int i = 0; i < 8; ++i) s = fmaf(cur[i], w1s[i * 8 + j], s);
            t1[j] = fmaxf(s, 0.f);
        }
        #pragma unroll
        for (int j = 0; j < 8; ++j) {
            float s = b2s[j];
            #pragma unroll
            for (int i = 0; i < 8; ++i) s = fmaf(t1[i], w2s[i * 8 + j], s);
            t2[j] = s;
        }
        #pragma unroll
        for (int j = 0; j < 8; ++j) cur[j] = t2[j];
    }
    #pragma unroll
    for (int h = 0; h < 8; ++h)
        g_ea[((size_t)(b * Hn + h)) * En + e] = cur[h];

    int u = edge_index[(size_t)b * 2 * En + e];
    int v = edge_index[(size_t)b * 2 * En + En + e];
    g_eid[((size_t)b * Nn + u) * Nn + v] = e + 1;
}

// ================= fused attention: 4 q-rows/warp, d split across half-warps ==
__global__ __launch_bounds__(256, 2) void attn_kernel(
    const float* __restrict__ adj,
    const float* __restrict__ shifts, const float* __restrict__ widths,
    const float* __restrict__ slW, float* __restrict__ out)
{
    __shared__ __align__(16) float Ks[2][KT][KPAD];
    __shared__ __align__(16) float Vs[2][KT][KPAD];
    __shared__ __align__(16) float Qs[CTAQ][KPAD];

    const int b = blockIdx.z, h = blockIdx.y;
    const int tid = threadIdx.x, warp = tid >> 5, lane = tid & 31;
    const int ln = lane & 15;        // key column within a 16-key pass
    const int dh = lane >> 4;        // d-half: 0 -> d[0:16), 1 -> d[16:32)
    const int qbase0 = blockIdx.x * CTAQ;
    const int qb = qbase0 + warp * QROWS;   // this warp's first q row

    const float shift  = __ldg(shifts + h);
    const float wd     = __ldg(widths + h);
    const float inv2w2 = 1.f / (2.f * wd * wd);
    const float slw    = __ldg(slW + h);

    const float* adjB = adj + ((size_t)b * Nn + qb) * Nn;
    const int*   eidB = g_eid + ((size_t)b * Nn + qb) * Nn;
    const float* eab  = g_ea + ((size_t)(b * Hn + h)) * En;

    const float* Kg = g_K + ((size_t)(b * Hn + h)) * Nn * DHn;
    const float* Vg = g_V + ((size_t)(b * Hn + h)) * Nn * DHn;

    unsigned ksBase = (unsigned)__cvta_generic_to_shared(&Ks[0][0][0]);
    unsigned vsBase = (unsigned)__cvta_generic_to_shared(&Vs[0][0][0]);

    auto load_tile = [&](int buf, int t) {
        const float* kg = Kg + (size_t)t * KT * DHn;
        const float* vg = Vg + (size_t)t * KT * DHn;
        #pragma unroll
        for (int it = 0; it < 2; ++it) {
            int i = tid + it * 256;
            int k = i >> 3, cc = i & 7;
            unsigned off = (unsigned)(((buf * KT + k) * KPAD) + cc * 4) * 4u;
            CP_ASYNC16(ksBase + off, kg + k * DHn + cc * 4);
            CP_ASYNC16(vsBase + off, vg + k * DHn + cc * 4);
        }
    };

    load_tile(0, 0);
    CP_COMMIT();

    // stage Q (pre-scaled) into shared: 32 rows x 32 d
    {
        const float* Qp = g_Q + (((size_t)(b * Hn + h)) * Nn + qbase0) * DHn;
        for (int i = tid; i < CTAQ * DHn; i += 256) {
            int rr = i >> 5, dd = i & 31;
            Qs[rr][dd] = Qp[i] * INVSCALE;
        }
    }

    ull acc[QROWS][8];
    #pragma unroll
    for (int r = 0; r < QROWS; ++r)
        #pragma unroll
        for (int i = 0; i < 8; ++i) acc[r][i] = 0ull;
    float m[QROWS], l[QROWS];
    #pragma unroll
    for (int r = 0; r < QROWS; ++r) { m[r] = -INFINITY; l[r] = 0.f; }

    for (int t = 0; t < NTILES; ++t) {
        if (t + 1 < NTILES) { load_tile((t + 1) & 1, t + 1); CP_COMMIT(); CP_WAIT1(); }
        else { CP_WAIT0(); }
        __syncthreads();

        const int buf = t & 1;
        float sv[4][QROWS];   // [pass][row] full biased scores

        // ---------- phase 1: scores for all 4 passes ----------
        #pragma unroll
        for (int p = 0; p < 4; ++p) {
            const int keyL = p * 16 + ln;
            const int kg   = t * KT + keyL;

            // bias loads first (overlap with the dot product)
            float av[QROWS]; int ev[QROWS];
            #pragma unroll
            for (int r = 0; r < QROWS; ++r) {
                av[r] = __ldg(adjB + (size_t)r * Nn + kg);
                ev[r] = __ldg(eidB + (size_t)r * Nn + kg);
            }

            const ulonglong2* Kp = (const ulonglong2*)&Ks[buf][keyL][dh * 16];
            ulonglong2 k0 = Kp[0], k1 = Kp[1], k2 = Kp[2], k3 = Kp[3];

            #pragma unroll
            for (int r = 0; r < QROWS; ++r) {
                const ulonglong2* Qp = (const ulonglong2*)&Qs[warp * QROWS + r][dh * 16];
                ulonglong2 q0 = Qp[0], q1 = Qp[1], q2 = Qp[2], q3 = Qp[3];
                ull sp = mul2(q0.x, k0.x);
                sp = fma2(q0.y, k0.y, sp);
                sp = fma2(q1.x, k1.x, sp);
                sp = fma2(q1.y, k1.y, sp);
                sp = fma2(q2.x, k2.x, sp);
                sp = fma2(q2.y, k2.y, sp);
                sp = fma2(q3.x, k3.x, sp);
                sp = fma2(q3.y, k3.y, sp);
                float sH = hsum2(sp);
                float sO = __shfl_xor_sync(0xffffffffu, sH, 16);
                // bias: moire (log of clipped gaussian) + edge + self-loop
                float dd = av[r] - shift;
                float bias = fmaxf(-dd * dd * inv2w2, LOGCLIP);
                if (ev[r]) bias += __ldg(eab + (ev[r] - 1));
                if (kg == qb + r) bias += slw;
                sv[p][r] = sH + sO + bias;
            }
        }

        // ---------- phase 2: one max-update per row per tile ----------
        #pragma unroll
        for (int r = 0; r < QROWS; ++r) {
            float tm = fmaxf(fmaxf(sv[0][r], sv[1][r]), fmaxf(sv[2][r], sv[3][r]));
            if (tm > m[r]) {
                float cc = __expf(m[r] - tm);
                l[r] *= cc; m[r] = tm;
                ull c2 = dup2(cc);
                #pragma unroll
                for (int i = 0; i < 8; ++i) acc[r][i] = mul2(acc[r][i], c2);
            }
        }

        // ---------- phase 3: P @ V ----------
        #pragma unroll
        for (int p = 0; p < 4; ++p) {
            const int keyL = p * 16 + ln;
            const ulonglong2* Vp = (const ulonglong2*)&Vs[buf][keyL][dh * 16];
            ulonglong2 v0 = Vp[0], v1 = Vp[1], v2 = Vp[2], v3 = Vp[3];
            #pragma unroll
            for (int r = 0; r < QROWS; ++r) {
                float pr = __expf(sv[p][r] - m[r]);
                l[r] += pr;
                ull pd = dup2(pr);
                acc[r][0] = fma2(pd, v0.x, acc[r][0]);
                acc[r][1] = fma2(pd, v0.y, acc[r][1]);
                acc[r][2] = fma2(pd, v1.x, acc[r][2]);
                acc[r][3] = fma2(pd, v1.y, acc[r][3]);
                acc[r][4] = fma2(pd, v2.x, acc[r][4]);
                acc[r][5] = fma2(pd, v2.y, acc[r][5]);
                acc[r][6] = fma2(pd, v3.x, acc[r][6]);
                acc[r][7] = fma2(pd, v3.y, acc[r][7]);
            }
        }
        __syncthreads();
    }

    // ---------- epilogue ----------
    // Each 16-lane half (dh fixed) independently covers ALL keys: lane ln
    // accumulated keys {ln, 16+ln, 32+ln, 48+ln} per tile. So the softmax
    // denominator l must be reduced over the 16 lanes of ONE half only
    // (xor 8,4,2,1) — summing across halves double-counts every key
    // (that was the R4 bug: rel_err == 0.5 exactly).
    // The acc reduce-scatter likewise stays within the half; lane ends
    // owning output element d == dh*16 + ln == lane.
    #pragma unroll
    for (int r = 0; r < QROWS; ++r) {
        float gm = m[r];
        #pragma unroll
        for (int o = 8; o > 0; o >>= 1)
            gm = fmaxf(gm, __shfl_xor_sync(0xffffffffu, gm, o));
        float cc = __expf(m[r] - gm);
        float ls = l[r] * cc;
        #pragma unroll
        for (int o = 8; o > 0; o >>= 1)
            ls += __shfl_xor_sync(0xffffffffu, ls, o);

        ull* arr = acc[r];
        ull c2 = dup2(cc);
        #pragma unroll
        for (int i = 0; i < 8; ++i) arr[i] = mul2(arr[i], c2);

        // stage xor 8: 8 ull -> 4
        {
            bool hiSel = (lane & 8) != 0;
            #pragma unroll
            for (int i = 0; i < 4; ++i) {
                ull kv = hiSel ? arr[4 + i] : arr[i];
                ull svv = hiSel ? arr[i] : arr[4 + i];
                ull rv = __shfl_xor_sync(0xffffffffu, svv, 8);
                arr[i] = add2(kv, rv);
            }
        }
        // stage xor 4: 4 -> 2
        {
            bool hiSel = (lane & 4) != 0;
            #pragma unroll
            for (int i = 0; i < 2; ++i) {
                ull kv = hiSel ? arr[2 + i] : arr[i];
                ull svv = hiSel ? arr[i] : arr[2 + i];
                ull rv = __shfl_xor_sync(0xffffffffu, svv, 4);
                arr[i] = add2(kv, rv);
            }
        }
        // stage xor 2: 2 -> 1
        {
            bool hiSel = (lane & 2) != 0;
            ull kv = hiSel ? arr[1] : arr[0];
            ull svv = hiSel ? arr[0] : arr[1];
            ull rv = __shfl_xor_sync(0xffffffffu, svv, 2);
            arr[0] = add2(kv, rv);
        }
        // stage xor 1: split final pair
        float lo, hi;
        unpack2(arr[0], lo, hi);
        bool hiSel = (lane & 1) != 0;
        float kf = hiSel ? hi : lo;
        float sf = hiSel ? lo : hi;
        float rf = __shfl_xor_sync(0xffffffffu, sf, 1);
        float res = kf + rf;

        // d == lane (dh*16 + (lane&15))
        out[((size_t)b * Nn + (qb + r)) * On + h * DHn + lane] = res / ls;
    }
}

// ================= launch =================
extern "C" void kernel_launch(void* const* d_in, const int* in_sizes, int n_in,
                              void* d_out, int out_size)
{
    const float* x         = (const float*)d_in[0];
    const float* adj       = (const float*)d_in[1];
    const float* edge_attr = (const float*)d_in[2];
    const float* qkv_w     = (const float*)d_in[3];
    const float* qkv_b     = (const float*)d_in[4];
    const float* e_w1      = (const float*)d_in[5];
    const float* e_b1      = (const float*)d_in[6];
    const float* e_w2      = (const float*)d_in[7];
    const float* e_b2      = (const float*)d_in[8];
    const float* shifts    = (const float*)d_in[9];
    const float* widths    = (const float*)d_in[10];
    const float* slW       = (const float*)d_in[11];
    const int*   edge_idx  = (const int*)d_in[12];
    float*       out       = (float*)d_out;

    qkv_kernel<<<dim3(12, 64), 256>>>(x, qkv_w, qkv_b);
    edge_kernel<<<(Bn * En) / 256, 256>>>(edge_attr, e_w1, e_b1, e_w2, e_b2, edge_idx);
    attn_kernel<<<dim3(Nn / CTAQ, Hn, Bn), 256>>>(adj, shifts, widths, slW, out);
}

// round 11
// speedup vs baseline: 2.8427x; 2.8427x over previous
#include <cuda_runtime.h>
#include <cuda_fp16.h>
#include <math.h>
#include <stdint.h>

#define Bn   2
#define Nn   2048
#define Hn   8
#define DHn  32
#define En   65536
#define DINn 256
#define On   256
#define INVSCALE 0.17677669529663687f
#define LOGCLIP  -13.815510557964274f

#define KT 64
#define NTILES (Nn / KT)

typedef uint32_t u32;

// -------- static device scratch --------
__device__ __half g_Qh[(size_t)Bn * Hn * Nn * DHn];
__device__ __half g_Ql[(size_t)Bn * Hn * Nn * DHn];
__device__ __half g_Kh[(size_t)Bn * Hn * Nn * DHn];
__device__ __half g_Kl[(size_t)Bn * Hn * Nn * DHn];
__device__ __half g_Vh[(size_t)Bn * Hn * Nn * DHn];
__device__ float  g_ea[(size_t)Bn * Hn * En];
// fragment-interleaved bias: [b][h][q>>4][k>>3][lane 0..31][4 halfs]
__device__ __half g_bias[(size_t)Bn * Hn * Nn * Nn];

#define CP_ASYNC16(smem_u32, gptr) \
    asm volatile("cp.async.cg.shared.global [%0], [%1], 16;" :: "r"(smem_u32), "l"(gptr))
#define CP_COMMIT() asm volatile("cp.async.commit_group;")
#define CP_WAIT1()  asm volatile("cp.async.wait_group 1;")
#define CP_WAIT0()  asm volatile("cp.async.wait_group 0;")

__device__ __forceinline__ u32 sptr(const void* p) {
    return (u32)__cvta_generic_to_shared(p);
}
#define LDSM4(r, addr) \
    asm volatile("ldmatrix.sync.aligned.m8n8.x4.shared.b16 {%0,%1,%2,%3}, [%4];" \
        : "=r"(r[0]), "=r"(r[1]), "=r"(r[2]), "=r"(r[3]) : "r"(addr))
#define LDSM4T(r, addr) \
    asm volatile("ldmatrix.sync.aligned.m8n8.x4.trans.shared.b16 {%0,%1,%2,%3}, [%4];" \
        : "=r"(r[0]), "=r"(r[1]), "=r"(r[2]), "=r"(r[3]) : "r"(addr))
#define MMA(c, a, b0, b1) \
    asm volatile("mma.sync.aligned.m16n8k16.row.col.f32.f16.f16.f32 " \
        "{%0,%1,%2,%3},{%4,%5,%6,%7},{%8,%9},{%0,%1,%2,%3};" \
        : "+f"(c[0]), "+f"(c[1]), "+f"(c[2]), "+f"(c[3]) \
        : "r"(a[0]), "r"(a[1]), "r"(a[2]), "r"(a[3]), "r"(b0), "r"(b1))

__device__ __forceinline__ u32 h2u(__half2 h) { u32 r; memcpy(&r, &h, 4); return r; }

// ================= QKV projection (fp32 GEMM -> split fp16) =================
__global__ __launch_bounds__(256) void qkv_kernel(
    const float* __restrict__ x, const float* __restrict__ w,
    const float* __restrict__ bias)
{
    __shared__ float As[16][68];
    __shared__ float Bs[16][68];
    const int tid = threadIdx.x;
    const int tx = tid & 15, ty = tid >> 4;
    const int row0 = blockIdx.y * 64;
    const int col0 = blockIdx.x * 64;

    float c[4][4] = {};
    for (int k0 = 0; k0 < DINn; k0 += 16) {
        {
            int kk = tid & 15, mb = tid >> 4;
            #pragma unroll
            for (int j = 0; j < 4; ++j) {
                int m = mb + j * 16;
                As[kk][m] = x[(size_t)(row0 + m) * DINn + k0 + kk];
            }
        }
        {
            int cc = tid & 63, kb = tid >> 6;
            #pragma unroll
            for (int j = 0; j < 4; ++j) {
                int kk = kb + j * 4;
                Bs[kk][cc] = w[(size_t)(k0 + kk) * 768 + col0 + cc];
            }
        }
        __syncthreads();
        #pragma unroll
        for (int kk = 0; kk < 16; ++kk) {
            float a[4], bb[4];
            #pragma unroll
            for (int i = 0; i < 4; ++i) a[i] = As[kk][ty * 4 + i];
            #pragma unroll
            for (int j = 0; j < 4; ++j) bb[j] = Bs[kk][tx * 4 + j];
            #pragma unroll
            for (int i = 0; i < 4; ++i)
                #pragma unroll
                for (int j = 0; j < 4; ++j)
                    c[i][j] = fmaf(a[i], bb[j], c[i][j]);
        }
        __syncthreads();
    }
    #pragma unroll
    for (int i = 0; i < 4; ++i) {
        int row = row0 + ty * 4 + i;
        int bb_ = row >> 11, n = row & (Nn - 1);
        #pragma unroll
        for (int j = 0; j < 4; ++j) {
            int col = col0 + tx * 4 + j;
            float v = c[i][j] + __ldg(bias + col);
            int s = col >> 8, hh = (col >> 5) & 7, d = col & 31;
            size_t idx = (((size_t)(bb_ * Hn + hh)) * Nn + n) * DHn + d;
            if (s == 0) {
                float vq = v * INVSCALE;
                __half hi = __float2half_rn(vq);
                g_Qh[idx] = hi;
                g_Ql[idx] = __float2half_rn(vq - __half2float(hi));
            } else if (s == 1) {
                __half hi = __float2half_rn(v);
                g_Kh[idx] = hi;
                g_Kl[idx] = __float2half_rn(v - __half2float(hi));
            } else {
                g_Vh[idx] = __float2half_rn(v);
            }
        }
    }
}

// ================= edge FFN =================
__global__ __launch_bounds__(256) void edge_kernel(
    const float* __restrict__ edge_attr,
    const float* __restrict__ e_w1, const float* __restrict__ e_b1,
    const float* __restrict__ e_w2, const float* __restrict__ e_b2)
{
    __shared__ float w1s[64], w2s[64], b1s[8], b2s[8];
    int tid = threadIdx.x;
    if (tid < 64) { w1s[tid] = e_w1[tid]; w2s[tid] = e_w2[tid]; }
    if (tid < 8)  { b1s[tid] = e_b1[tid]; b2s[tid] = e_b2[tid]; }
    __syncthreads();

    int gid = blockIdx.x * 256 + tid;
    int b = gid >> 16;
    int e = gid & (En - 1);

    float cur[8];
    const float* ap = edge_attr + ((size_t)b * En + e) * Hn;
    #pragma unroll
    for (int i = 0; i < 8; ++i) cur[i] = ap[i];

    #pragma unroll
    for (int pass = 0; pass < 2; ++pass) {
        float t1[8], t2[8];
        #pragma unroll
        for (int j = 0; j < 8; ++j) {
            float s = b1s[j];
            #pragma unroll
            for (int i = 0; i < 8; ++i) s = fmaf(cur[i], w1s[i * 8 + j], s);
            t1[j] = fmaxf(s, 0.f);
        }
        #pragma unroll
        for (int j = 0; j < 8; ++j) {
            float s = b2s[j];
            #pragma unroll
            for (int i = 0; i < 8; ++i) s = fmaf(t1[i], w2s[i * 8 + j], s);
            t2[j] = s;
        }
        #pragma unroll
        for (int j = 0; j < 8; ++j) cur[j] = t2[j];
    }
    #pragma unroll
    for (int h = 0; h < 8; ++h)
        g_ea[((size_t)(b * Hn + h)) * En + e] = cur[h];
}

// ====== dense bias (moire + self-loop) in fragment-interleaved fp16 ======
// half index for (b,h,q,k):
//   chunk = ((b*8+h)*128 + q>>4)*256 + k>>3
//   off   = ((q&7)*4 + ((k&7)>>1))*4 + ((q>>3)&1)*2 + (k&1)
__global__ __launch_bounds__(256) void bias_kernel(
    const float* __restrict__ adj,
    const float* __restrict__ shifts, const float* __restrict__ widths,
    const float* __restrict__ slW)
{
    int idx = blockIdx.x * 256 + threadIdx.x;  // B*N*(N/8) = 1M
    int q    = idx & (Nn - 1);
    int rest = idx >> 11;
    int k8   = rest & 255;
    int b    = rest >> 8;

    const float* ap = adj + ((size_t)b * Nn + q) * Nn + k8 * 8;
    float4 a0 = *(const float4*)ap;
    float4 a1 = *(const float4*)(ap + 4);
    float a[8] = {a0.x, a0.y, a0.z, a0.w, a1.x, a1.y, a1.z, a1.w};
    int dq = q - k8 * 8;  // diagonal position if in [0,8)

    size_t inoff = (size_t)((q & 7) * 16 + ((q >> 3) & 1) * 2);
    #pragma unroll
    for (int h = 0; h < 8; ++h) {
        float sh = __ldg(shifts + h);
        float wd = __ldg(widths + h);
        float inv2w2 = 1.f / (2.f * wd * wd);
        float sl = __ldg(slW + h);
        size_t base = ((((size_t)(b * 8 + h)) * 128 + (q >> 4)) * 256 + k8) * 128 + inoff;
        #pragma unroll
        for (int jj = 0; jj < 4; ++jj) {
            float d0 = a[2 * jj]     - sh;
            float d1 = a[2 * jj + 1] - sh;
            float z0 = fmaxf(-d0 * d0 * inv2w2, LOGCLIP);
            float z1 = fmaxf(-d1 * d1 * inv2w2, LOGCLIP);
            if (2 * jj == dq)     z0 += sl;
            if (2 * jj + 1 == dq) z1 += sl;
            *(__half2*)(g_bias + base + jj * 4) = __floats2half2_rn(z0, z1);
        }
    }
}

// ====== scatter edge bias (unique (b,u,v) -> unique address per h) ======
__global__ __launch_bounds__(256) void edge_scatter_kernel(
    const int* __restrict__ edge_index)
{
    int gid = blockIdx.x * 256 + threadIdx.x;  // B*E
    int b = gid >> 16;
    int e = gid & (En - 1);
    int u = edge_index[(size_t)b * 2 * En + e];
    int v = edge_index[(size_t)b * 2 * En + En + e];
    size_t inoff = (size_t)(((u & 7) * 4 + ((v & 7) >> 1)) * 4 + ((u >> 3) & 1) * 2 + (v & 1));
    #pragma unroll
    for (int h = 0; h < 8; ++h) {
        float ea = g_ea[((size_t)(b * 8 + h)) * En + e];
        size_t a = ((((size_t)(b * 8 + h)) * 128 + (u >> 4)) * 256 + (v >> 3)) * 128 + inoff;
        g_bias[a] = __float2half_rn(__half2float(g_bias[a]) + ea);
    }
}

// ================= tensor-core attention =================
// CTA: 128 thr (4 warps), 64 q rows; warp -> 16 rows; KT=64 keys double-buffered
__global__ __launch_bounds__(128) void attn_kernel(float* __restrict__ out)
{
    __shared__ __align__(16) __half sKh[2][64][40];  // rows padded to 80B
    __shared__ __align__(16) __half sKl[2][64][40];
    __shared__ __align__(16) __half sV [2][64][40];
    __shared__ __align__(16) __half sQh[64][40];
    __shared__ __align__(16) __half sQl[64][40];

    const int b = blockIdx.z, h = blockIdx.y;
    const int tid = threadIdx.x, warp = tid >> 5, lane = tid & 31;
    const int qb0 = blockIdx.x * 64;
    const int qbw = qb0 + warp * 16;

    const size_t plane = ((size_t)(b * Hn + h)) * Nn * DHn;
    const __half* gKh = g_Kh + plane;
    const __half* gKl = g_Kl + plane;
    const __half* gV  = g_Vh + plane;
    const __half* gB  = g_bias +
        ((((size_t)(b * Hn + h)) * 128 + (qbw >> 4)) * 256) * 128 + lane * 4;

    auto load_tile = [&](int buf, int t) {
        #pragma unroll
        for (int m = 0; m < 2; ++m) {
            int i = tid + m * 128;           // 256 chunks per matrix
            int row = i >> 2, c = (i & 3) * 8;
            const __half* s;
            s = gKh + (size_t)t * KT * DHn + row * DHn + c;
            CP_ASYNC16(sptr(&sKh[buf][row][c]), s);
            s = gKl + (size_t)t * KT * DHn + row * DHn + c;
            CP_ASYNC16(sptr(&sKl[buf][row][c]), s);
            s = gV + (size_t)t * KT * DHn + row * DHn + c;
            CP_ASYNC16(sptr(&sV[buf][row][c]), s);
        }
    };

    load_tile(0, 0);
    CP_COMMIT();

    // stage Q tile (64 rows) into smem
    {
        const __half* gqh = g_Qh + plane + (size_t)qb0 * DHn;
        const __half* gql = g_Ql + plane + (size_t)qb0 * DHn;
        for (int i = tid; i < 256; i += 128) {
            int row = i >> 2, c = (i & 3) * 8;
            *(uint4*)&sQh[row][c] = *(const uint4*)(gqh + row * DHn + c);
            *(uint4*)&sQl[row][c] = *(const uint4*)(gql + row * DHn + c);
        }
    }
    __syncthreads();

    // Q A-fragments (held all kernel)
    u32 qh[2][4], ql[2][4];
    {
        int rowQ = warp * 16 + (lane & 7) + ((lane >> 3) & 1) * 8;
        int colQ = (lane >> 4) * 8;
        #pragma unroll
        for (int t = 0; t < 2; ++t) {
            LDSM4(qh[t], sptr(&sQh[rowQ][t * 16 + colQ]));
            LDSM4(ql[t], sptr(&sQl[rowQ][t * 16 + colQ]));
        }
    }

    const int rK = (lane & 7) + ((lane >> 4) & 1) * 8;
    const int cK = ((lane >> 3) & 1) * 8;
    const int rV = (lane & 7) + ((lane >> 3) & 1) * 8;
    const int cV = (lane >> 4) * 8;

    float O[4][4] = {};
    float mA = -INFINITY, mB = -INFINITY, lA = 0.f, lB = 0.f;

    for (int t = 0; t < NTILES; ++t) {
        if (t + 1 < NTILES) { load_tile((t + 1) & 1, t + 1); CP_COMMIT(); CP_WAIT1(); }
        else { CP_WAIT0(); }
        __syncthreads();
        const int buf = t & 1;

        float S[8][4];
        #pragma unroll
        for (int j = 0; j < 8; ++j)
            #pragma unroll
            for (int i = 0; i < 4; ++i) S[j][i] = 0.f;

        // ---- QK^T (3-term fp16 split) ----
        #pragma unroll
        for (int g = 0; g < 4; ++g) {
            u32 kh0[4], kh1[4], kl0[4], kl1[4];
            LDSM4(kh0, sptr(&sKh[buf][16 * g + rK][cK]));
            LDSM4(kh1, sptr(&sKh[buf][16 * g + rK][16 + cK]));
            LDSM4(kl0, sptr(&sKl[buf][16 * g + rK][cK]));
            LDSM4(kl1, sptr(&sKl[buf][16 * g + rK][16 + cK]));
            float* s0 = S[2 * g];
            float* s1 = S[2 * g + 1];
            MMA(s0, qh[0], kh0[0], kh0[1]); MMA(s0, qh[1], kh1[0], kh1[1]);
            MMA(s0, ql[0], kh0[0], kh0[1]); MMA(s0, ql[1], kh1[0], kh1[1]);
            MMA(s0, qh[0], kl0[0], kl0[1]); MMA(s0, qh[1], kl1[0], kl1[1]);
            MMA(s1, qh[0], kh0[2], kh0[3]); MMA(s1, qh[1], kh1[2], kh1[3]);
            MMA(s1, ql[0], kh0[2], kh0[3]); MMA(s1, ql[1], kh1[2], kh1[3]);
            MMA(s1, qh[0], kl0[2], kl0[3]); MMA(s1, qh[1], kl1[2], kl1[3]);
        }

        // ---- bias add (fragment-interleaved fp16, coalesced LDG.64) ----
        {
            const __half* bp = gB + (size_t)(t * 8) * 128;
            #pragma unroll
            for (int j = 0; j < 8; ++j) {
                uint2 u = *(const uint2*)(bp + (size_t)j * 128);
                __half2 hA, hB; memcpy(&hA, &u.x, 4); memcpy(&hB, &u.y, 4);
                float2 fa = __half22float2(hA);
                float2 fb = __half22float2(hB);
                S[j][0] += fa.x; S[j][1] += fa.y;
                S[j][2] += fb.x; S[j][3] += fb.y;
            }
        }

        // ---- online softmax (rows rA = lane/4, rB = rA+8) ----
        float tmA = -INFINITY, tmB = -INFINITY;
        #pragma unroll
        for (int j = 0; j < 8; ++j) {
            tmA = fmaxf(tmA, fmaxf(S[j][0], S[j][1]));
            tmB = fmaxf(tmB, fmaxf(S[j][2], S[j][3]));
        }
        tmA = fmaxf(tmA, __shfl_xor_sync(0xffffffffu, tmA, 1));
        tmA = fmaxf(tmA, __shfl_xor_sync(0xffffffffu, tmA, 2));
        tmB = fmaxf(tmB, __shfl_xor_sync(0xffffffffu, tmB, 1));
        tmB = fmaxf(tmB, __shfl_xor_sync(0xffffffffu, tmB, 2));
        float mnA = fmaxf(mA, tmA), mnB = fmaxf(mB, tmB);
        float capA = __expf(mA - mnA), capB = __expf(mB - mnB);
        mA = mnA; mB = mnB;
        lA *= capA; lB *= capB;
        #pragma unroll
        for (int j = 0; j < 4; ++j) {
            O[j][0] *= capA; O[j][1] *= capA;
            O[j][2] *= capB; O[j][3] *= capB;
        }

        // ---- exp -> split fp16 P fragments ----
        u32 Ph[4][4], Pl[4][4];
        float sumA = 0.f, sumB = 0.f;
        #pragma unroll
        for (int j = 0; j < 8; ++j) {
            float p0 = __expf(S[j][0] - mA), p1 = __expf(S[j][1] - mA);
            float p2 = __expf(S[j][2] - mB), p3 = __expf(S[j][3] - mB);
            sumA += p0 + p1; sumB += p2 + p3;
            __half2 h01 = __floats2half2_rn(p0, p1);
            __half2 h23 = __floats2half2_rn(p2, p3);
            float2 r01 = __half22float2(h01);
            float2 r23 = __half22float2(h23);
            __half2 e01 = __floats2half2_rn(p0 - r01.x, p1 - r01.y);
            __half2 e23 = __floats2half2_rn(p2 - r23.x, p3 - r23.y);
            int g = j >> 1, ix = (j & 1) * 2;
            Ph[g][ix] = h2u(h01); Ph[g][ix + 1] = h2u(h23);
            Pl[g][ix] = h2u(e01); Pl[g][ix + 1] = h2u(e23);
        }
        lA += sumA; lB += sumB;

        // ---- P @ V ----
        #pragma unroll
        for (int g = 0; g < 4; ++g) {
            u32 v0[4], v1[4];
            LDSM4T(v0, sptr(&sV[buf][16 * g + rV][cV]));
            LDSM4T(v1, sptr(&sV[buf][16 * g + rV][16 + cV]));
            MMA(O[0], Ph[g], v0[0], v0[1]); MMA(O[1], Ph[g], v0[2], v0[3]);
            MMA(O[2], Ph[g], v1[0], v1[1]); MMA(O[3], Ph[g], v1[2], v1[3]);
            MMA(O[0], Pl[g], v0[0], v0[1]); MMA(O[1], Pl[g], v0[2], v0[3]);
            MMA(O[2], Pl[g], v1[0], v1[1]); MMA(O[3], Pl[g], v1[2], v1[3]);
        }
        __syncthreads();
    }

    // ---- epilogue: quad-reduce l, normalize, write ----
    lA += __shfl_xor_sync(0xffffffffu, lA, 1);
    lA += __shfl_xor_sync(0xffffffffu, lA, 2);
    lB += __shfl_xor_sync(0xffffffffu, lB, 1);
    lB += __shfl_xor_sync(0xffffffffu, lB, 2);
    float iA = 1.f / lA, iB = 1.f / lB;
    int rA = qbw + (lane >> 2), rB = rA + 8;
    int cb = h * DHn + 2 * (lane & 3);
    #pragma unroll
    for (int j = 0; j < 4; ++j) {
        float2 oa = { O[j][0] * iA, O[j][1] * iA };
        float2 ob = { O[j][2] * iB, O[j][3] * iB };
        *(float2*)&out[(size_t)(b * Nn + rA) * On + cb + 8 * j] = oa;
        *(float2*)&out[(size_t)(b * Nn + rB) * On + cb + 8 * j] = ob;
    }
}

// ================= launch =================
extern "C" void kernel_launch(void* const* d_in, const int* in_sizes, int n_in,
                              void* d_out, int out_size)
{
    const float* x         = (const float*)d_in[0];
    const float* adj       = (const float*)d_in[1];
    const float* edge_attr = (const float*)d_in[2];
    const float* qkv_w     = (const float*)d_in[3];
    const float* qkv_b     = (const float*)d_in[4];
    const float* e_w1      = (const float*)d_in[5];
    const float* e_b1      = (const float*)d_in[6];
    const float* e_w2      = (const float*)d_in[7];
    const float* e_b2      = (const float*)d_in[8];
    const float* shifts    = (const float*)d_in[9];
    const float* widths    = (const float*)d_in[10];
    const float* slW       = (const float*)d_in[11];
    const int*   edge_idx  = (const int*)d_in[12];
    float*       out       = (float*)d_out;

    qkv_kernel<<<dim3(12, 64), 256>>>(x, qkv_w, qkv_b);
    edge_kernel<<<(Bn * En) / 256, 256>>>(edge_attr, e_w1, e_b1, e_w2, e_b2);
    bias_kernel<<<(Bn * Nn * (Nn / 8)) / 256, 256>>>(adj, shifts, widths, slW);
    edge_scatter_kernel<<<(Bn * En) / 256, 256>>>(edge_idx);
    attn_kernel<<<dim3(Nn / 64, Hn, Bn), 128>>>(out);
}

// round 12
// speedup vs baseline: 3.1130x; 1.0951x over previous
#include <cuda_runtime.h>
#include <cuda_fp16.h>
#include <math.h>
#include <stdint.h>

#define Bn   2
#define Nn   2048
#define Hn   8
#define DHn  32
#define En   65536
#define DINn 256
#define On   256
#define INVSCALE 0.17677669529663687f
#define LOGCLIP  -13.815510557964274f

#define KT 64
#define NTILES (Nn / KT)

typedef uint32_t u32;

// -------- static device scratch --------
__device__ __half g_Qh[(size_t)Bn * Hn * Nn * DHn];
__device__ __half g_Ql[(size_t)Bn * Hn * Nn * DHn];
__device__ __half g_Kh[(size_t)Bn * Hn * Nn * DHn];
__device__ __half g_Kl[(size_t)Bn * Hn * Nn * DHn];
__device__ __half g_Vh[(size_t)Bn * Hn * Nn * DHn];
// fragment-interleaved bias: [b][h][q>>4][k>>3][lane 0..31][4 halfs]
__device__ __half g_bias[(size_t)Bn * Hn * Nn * Nn];
// split-fp16 copies of x and qkv_w for the tensor-core projection
__device__ __half g_xh[(size_t)Bn * Nn * DINn];
__device__ __half g_xl[(size_t)Bn * Nn * DINn];
__device__ __half g_wh[(size_t)DINn * 768];
__device__ __half g_wl[(size_t)DINn * 768];

#define CP_ASYNC16(smem_u32, gptr) \
    asm volatile("cp.async.cg.shared.global [%0], [%1], 16;" :: "r"(smem_u32), "l"(gptr))
#define CP_COMMIT() asm volatile("cp.async.commit_group;")
#define CP_WAIT1()  asm volatile("cp.async.wait_group 1;")
#define CP_WAIT0()  asm volatile("cp.async.wait_group 0;")

__device__ __forceinline__ u32 sptr(const void* p) {
    return (u32)__cvta_generic_to_shared(p);
}
#define LDSM4(r, addr) \
    asm volatile("ldmatrix.sync.aligned.m8n8.x4.shared.b16 {%0,%1,%2,%3}, [%4];" \
        : "=r"(r[0]), "=r"(r[1]), "=r"(r[2]), "=r"(r[3]) : "r"(addr))
#define LDSM4T(r, addr) \
    asm volatile("ldmatrix.sync.aligned.m8n8.x4.trans.shared.b16 {%0,%1,%2,%3}, [%4];" \
        : "=r"(r[0]), "=r"(r[1]), "=r"(r[2]), "=r"(r[3]) : "r"(addr))
#define MMA(c, a, b0, b1) \
    asm volatile("mma.sync.aligned.m16n8k16.row.col.f32.f16.f16.f32 " \
        "{%0,%1,%2,%3},{%4,%5,%6,%7},{%8,%9},{%0,%1,%2,%3};" \
        : "+f"(c[0]), "+f"(c[1]), "+f"(c[2]), "+f"(c[3]) \
        : "r"(a[0]), "r"(a[1]), "r"(a[2]), "r"(a[3]), "r"(b0), "r"(b1))

__device__ __forceinline__ u32 h2u(__half2 h) { u32 r; memcpy(&r, &h, 4); return r; }

// ================= fp32 -> split fp16 conversion (x and w) =================
__global__ __launch_bounds__(256) void convert_kernel(
    const float* __restrict__ x, const float* __restrict__ w)
{
    int i = blockIdx.x * 256 + threadIdx.x;
    const int NX = Bn * Nn * DINn;          // 1048576
    if (i < NX) {
        float v = x[i];
        __half hi = __float2half_rn(v);
        g_xh[i] = hi;
        g_xl[i] = __float2half_rn(v - __half2float(hi));
    } else {
        int j = i - NX;
        if (j < DINn * 768) {
            float v = w[j];
            __half hi = __float2half_rn(v);
            g_wh[j] = hi;
            g_wl[j] = __float2half_rn(v - __half2float(hi));
        }
    }
}

// ================= QKV projection: split-fp16 tensor-core GEMM ==============
// C(4096x768) = x(4096x256) @ w(256x768); 3-term split (xh*wh + xl*wh + xh*wl)
// CTA: 128 thr / 4 warps; tile M=64, N=64; K chunks of 32, double-buffered.
#define QK_PADX 40
#define QK_PADW 72
__global__ __launch_bounds__(128) void qkv_mma_kernel(const float* __restrict__ bias)
{
    __shared__ __align__(16) __half sXh[2][64][QK_PADX];
    __shared__ __align__(16) __half sXl[2][64][QK_PADX];
    __shared__ __align__(16) __half sWh[2][32][QK_PADW];
    __shared__ __align__(16) __half sWl[2][32][QK_PADW];

    const int tid = threadIdx.x, warp = tid >> 5, lane = tid & 31;
    const int row0 = blockIdx.y * 64;
    const int col0 = blockIdx.x * 64;

    auto load_tile = [&](int buf, int k0) {
        // X: 64 rows x 32 halfs (hi+lo): 256 16B-chunks each
        #pragma unroll
        for (int m = 0; m < 2; ++m) {
            int i = tid + m * 128;
            int r = i >> 2, c = (i & 3) * 8;
            const __half* s = g_xh + (size_t)(row0 + r) * DINn + k0 + c;
            CP_ASYNC16(sptr(&sXh[buf][r][c]), s);
            s = g_xl + (size_t)(row0 + r) * DINn + k0 + c;
            CP_ASYNC16(sptr(&sXl[buf][r][c]), s);
        }
        // W: 32 rows x 64 halfs (hi+lo): 256 16B-chunks each
        #pragma unroll
        for (int m = 0; m < 2; ++m) {
            int i = tid + m * 128;
            int r = i >> 3, c = (i & 7) * 8;
            const __half* s = g_wh + (size_t)(k0 + r) * 768 + col0 + c;
            CP_ASYNC16(sptr(&sWh[buf][r][c]), s);
            s = g_wl + (size_t)(k0 + r) * 768 + col0 + c;
            CP_ASYNC16(sptr(&sWl[buf][r][c]), s);
        }
    };

    load_tile(0, 0);
    CP_COMMIT();

    float C[8][4];
    #pragma unroll
    for (int j = 0; j < 8; ++j)
        #pragma unroll
        for (int i = 0; i < 4; ++i) C[j][i] = 0.f;

    const int rA = warp * 16 + (lane & 15);     // A ldmatrix row
    const int cA = (lane >> 4) * 8;
    const int rB = (lane & 7) + ((lane >> 3) & 1) * 8;   // B ldmatrix (trans)
    const int cB = (lane >> 4) * 8;

    for (int kc = 0; kc < 8; ++kc) {
        if (kc + 1 < 8) { load_tile((kc + 1) & 1, (kc + 1) * 32); CP_COMMIT(); CP_WAIT1(); }
        else { CP_WAIT0(); }
        __syncthreads();
        const int buf = kc & 1;

        #pragma unroll
        for (int ks = 0; ks < 2; ++ks) {        // two k16 steps per chunk
            const int ko = ks * 16;
            u32 ah[4], al[4];
            LDSM4(ah, sptr(&sXh[buf][rA][ko + cA]));
            LDSM4(al, sptr(&sXl[buf][rA][ko + cA]));
            #pragma unroll
            for (int g = 0; g < 4; ++g) {       // 4 n16 blocks
                u32 wh[4], wl[4];
                LDSM4T(wh, sptr(&sWh[buf][ko + rB][g * 16 + cB]));
                LDSM4T(wl, sptr(&sWl[buf][ko + rB][g * 16 + cB]));
                MMA(C[2 * g],     ah, wh[0], wh[1]);
                MMA(C[2 * g + 1], ah, wh[2], wh[3]);
                MMA(C[2 * g],     al, wh[0], wh[1]);
                MMA(C[2 * g + 1], al, wh[2], wh[3]);
                MMA(C[2 * g],     ah, wl[0], wl[1]);
                MMA(C[2 * g + 1], ah, wl[2], wl[3]);
            }
        }
        __syncthreads();
    }

    // epilogue: add bias, decode (s,h,d), split-store
    #pragma unroll
    for (int j = 0; j < 8; ++j) {
        #pragma unroll
        for (int i = 0; i < 4; ++i) {
            int row = row0 + warp * 16 + (lane >> 2) + (i >> 1) * 8;
            int col = col0 + j * 8 + 2 * (lane & 3) + (i & 1);
            float v = C[j][i] + __ldg(bias + col);
            int bb = row >> 11, n = row & (Nn - 1);
            int s = col >> 8, hh = (col >> 5) & 7, d = col & 31;
            size_t idx = (((size_t)(bb * Hn + hh)) * Nn + n) * DHn + d;
            if (s == 0) {
                float vq = v * INVSCALE;
                __half hi = __float2half_rn(vq);
                g_Qh[idx] = hi;
                g_Ql[idx] = __float2half_rn(vq - __half2float(hi));
            } else if (s == 1) {
                __half hi = __float2half_rn(v);
                g_Kh[idx] = hi;
                g_Kl[idx] = __float2half_rn(v - __half2float(hi));
            } else {
                g_Vh[idx] = __float2half_rn(v);
            }
        }
    }
}

// ====== dense bias (moire + self-loop) in fragment-interleaved fp16 ======
__global__ __launch_bounds__(256) void bias_kernel(
    const float* __restrict__ adj,
    const float* __restrict__ shifts, const float* __restrict__ widths,
    const float* __restrict__ slW)
{
    int idx = blockIdx.x * 256 + threadIdx.x;  // B*N*(N/8) = 1M
    int q    = idx & (Nn - 1);
    int rest = idx >> 11;
    int k8   = rest & 255;
    int b    = rest >> 8;

    const float* ap = adj + ((size_t)b * Nn + q) * Nn + k8 * 8;
    float4 a0 = *(const float4*)ap;
    float4 a1 = *(const float4*)(ap + 4);
    float a[8] = {a0.x, a0.y, a0.z, a0.w, a1.x, a1.y, a1.z, a1.w};
    int dq = q - k8 * 8;  // diagonal position if in [0,8)

    size_t inoff = (size_t)((q & 7) * 16 + ((q >> 3) & 1) * 2);
    #pragma unroll
    for (int h = 0; h < 8; ++h) {
        float sh = __ldg(shifts + h);
        float wd = __ldg(widths + h);
        float inv2w2 = 1.f / (2.f * wd * wd);
        float sl = __ldg(slW + h);
        size_t base = ((((size_t)(b * 8 + h)) * 128 + (q >> 4)) * 256 + k8) * 128 + inoff;
        #pragma unroll
        for (int jj = 0; jj < 4; ++jj) {
            float d0 = a[2 * jj]     - sh;
            float d1 = a[2 * jj + 1] - sh;
            float z0 = fmaxf(-d0 * d0 * inv2w2, LOGCLIP);
            float z1 = fmaxf(-d1 * d1 * inv2w2, LOGCLIP);
            if (2 * jj == dq)     z0 += sl;
            if (2 * jj + 1 == dq) z1 += sl;
            *(__half2*)(g_bias + base + jj * 4) = __floats2half2_rn(z0, z1);
        }
    }
}

// ====== fused edge FFN + scatter into dense bias ======
// (b,u,v) unique per batch -> unique address per h -> plain RMW is safe.
// MUST run after bias_kernel.
__global__ __launch_bounds__(256) void edge_fused_kernel(
    const float* __restrict__ edge_attr,
    const float* __restrict__ e_w1, const float* __restrict__ e_b1,
    const float* __restrict__ e_w2, const float* __restrict__ e_b2,
    const int*   __restrict__ edge_index)
{
    __shared__ float w1s[64], w2s[64], b1s[8], b2s[8];
    int tid = threadIdx.x;
    if (tid < 64) { w1s[tid] = e_w1[tid]; w2s[tid] = e_w2[tid]; }
    if (tid < 8)  { b1s[tid] = e_b1[tid]; b2s[tid] = e_b2[tid]; }
    __syncthreads();

    int gid = blockIdx.x * 256 + tid;
    int b = gid >> 16;
    int e = gid & (En - 1);

    // prefetch indices early (hide latency under FFN math)
    int u = edge_index[(size_t)b * 2 * En + e];
    int v = edge_index[(size_t)b * 2 * En + En + e];

    float cur[8];
    const float* ap = edge_attr + ((size_t)b * En + e) * Hn;
    #pragma unroll
    for (int i = 0; i < 8; ++i) cur[i] = ap[i];

    #pragma unroll
    for (int pass = 0; pass < 2; ++pass) {
        float t1[8], t2[8];
        #pragma unroll
        for (int j = 0; j < 8; ++j) {
            float s = b1s[j];
            #pragma unroll
            for (int i = 0; i < 8; ++i) s = fmaf(cur[i], w1s[i * 8 + j], s);
            t1[j] = fmaxf(s, 0.f);
        }
        #pragma unroll
        for (int j = 0; j < 8; ++j) {
            float s = b2s[j];
            #pragma unroll
            for (int i = 0; i < 8; ++i) s = fmaf(t1[i], w2s[i * 8 + j], s);
            t2[j] = s;
        }
        #pragma unroll
        for (int j = 0; j < 8; ++j) cur[j] = t2[j];
    }

    size_t inoff = (size_t)(((u & 7) * 4 + ((v & 7) >> 1)) * 4 + ((u >> 3) & 1) * 2 + (v & 1));
    #pragma unroll
    for (int h = 0; h < 8; ++h) {
        size_t a = ((((size_t)(b * 8 + h)) * 128 + (u >> 4)) * 256 + (v >> 3)) * 128 + inoff;
        g_bias[a] = __float2half_rn(__half2float(g_bias[a]) + cur[h]);
    }
}

// ================= tensor-core attention =================
// CTA: 128 thr (4 warps), 64 q rows; warp -> 16 rows; KT=64 keys double-buffered
__global__ __launch_bounds__(128) void attn_kernel(float* __restrict__ out)
{
    __shared__ __align__(16) __half sKh[2][64][40];  // rows padded to 80B
    __shared__ __align__(16) __half sKl[2][64][40];
    __shared__ __align__(16) __half sV [2][64][40];
    __shared__ __align__(16) __half sQh[64][40];
    __shared__ __align__(16) __half sQl[64][40];

    const int b = blockIdx.z, h = blockIdx.y;
    const int tid = threadIdx.x, warp = tid >> 5, lane = tid & 31;
    const int qb0 = blockIdx.x * 64;
    const int qbw = qb0 + warp * 16;

    const size_t plane = ((size_t)(b * Hn + h)) * Nn * DHn;
    const __half* gKh = g_Kh + plane;
    const __half* gKl = g_Kl + plane;
    const __half* gV  = g_Vh + plane;
    const __half* gB  = g_bias +
        ((((size_t)(b * Hn + h)) * 128 + (qbw >> 4)) * 256) * 128 + lane * 4;

    auto load_tile = [&](int buf, int t) {
        #pragma unroll
        for (int m = 0; m < 2; ++m) {
            int i = tid + m * 128;           // 256 chunks per matrix
            int row = i >> 2, c = (i & 3) * 8;
            const __half* s;
            s = gKh + (size_t)t * KT * DHn + row * DHn + c;
            CP_ASYNC16(sptr(&sKh[buf][row][c]), s);
            s = gKl + (size_t)t * KT * DHn + row * DHn + c;
            CP_ASYNC16(sptr(&sKl[buf][row][c]), s);
            s = gV + (size_t)t * KT * DHn + row * DHn + c;
            CP_ASYNC16(sptr(&sV[buf][row][c]), s);
        }
    };

    load_tile(0, 0);
    CP_COMMIT();

    // stage Q tile (64 rows) into smem
    {
        const __half* gqh = g_Qh + plane + (size_t)qb0 * DHn;
        const __half* gql = g_Ql + plane + (size_t)qb0 * DHn;
        for (int i = tid; i < 256; i += 128) {
            int row = i >> 2, c = (i & 3) * 8;
            *(uint4*)&sQh[row][c] = *(const uint4*)(gqh + row * DHn + c);
            *(uint4*)&sQl[row][c] = *(const uint4*)(gql + row * DHn + c);
        }
    }
    __syncthreads();

    // Q A-fragments (held all kernel)
    u32 qh[2][4], ql[2][4];
    {
        int rowQ = warp * 16 + (lane & 7) + ((lane >> 3) & 1) * 8;
        int colQ = (lane >> 4) * 8;
        #pragma unroll
        for (int t = 0; t < 2; ++t) {
            LDSM4(qh[t], sptr(&sQh[rowQ][t * 16 + colQ]));
            LDSM4(ql[t], sptr(&sQl[rowQ][t * 16 + colQ]));
        }
    }

    const int rK = (lane & 7) + ((lane >> 4) & 1) * 8;
    const int cK = ((lane >> 3) & 1) * 8;
    const int rV = (lane & 7) + ((lane >> 3) & 1) * 8;
    const int cV = (lane >> 4) * 8;

    float O[4][4] = {};
    float mA = -INFINITY, mB = -INFINITY, lA = 0.f, lB = 0.f;

    for (int t = 0; t < NTILES; ++t) {
        if (t + 1 < NTILES) { load_tile((t + 1) & 1, t + 1); CP_COMMIT(); CP_WAIT1(); }
        else { CP_WAIT0(); }
        __syncthreads();
        const int buf = t & 1;

        float S[8][4];
        #pragma unroll
        for (int j = 0; j < 8; ++j)
            #pragma unroll
            for (int i = 0; i < 4; ++i) S[j][i] = 0.f;

        // ---- QK^T (3-term fp16 split) ----
        #pragma unroll
        for (int g = 0; g < 4; ++g) {
            u32 kh0[4], kh1[4], kl0[4], kl1[4];
            LDSM4(kh0, sptr(&sKh[buf][16 * g + rK][cK]));
            LDSM4(kh1, sptr(&sKh[buf][16 * g + rK][16 + cK]));
            LDSM4(kl0, sptr(&sKl[buf][16 * g + rK][cK]));
            LDSM4(kl1, sptr(&sKl[buf][16 * g + rK][16 + cK]));
            float* s0 = S[2 * g];
            float* s1 = S[2 * g + 1];
            MMA(s0, qh[0], kh0[0], kh0[1]); MMA(s0, qh[1], kh1[0], kh1[1]);
            MMA(s0, ql[0], kh0[0], kh0[1]); MMA(s0, ql[1], kh1[0], kh1[1]);
            MMA(s0, qh[0], kl0[0], kl0[1]); MMA(s0, qh[1], kl1[0], kl1[1]);
            MMA(s1, qh[0], kh0[2], kh0[3]); MMA(s1, qh[1], kh1[2], kh1[3]);
            MMA(s1, ql[0], kh0[2], kh0[3]); MMA(s1, ql[1], kh1[2], kh1[3]);
            MMA(s1, qh[0], kl0[2], kl0[3]); MMA(s1, qh[1], kl1[2], kl1[3]);
        }

        // ---- bias add (fragment-interleaved fp16, coalesced LDG.64) ----
        {
            const __half* bp = gB + (size_t)(t * 8) * 128;
            #pragma unroll
            for (int j = 0; j < 8; ++j) {
                uint2 u = *(const uint2*)(bp + (size_t)j * 128);
                __half2 hA, hB; memcpy(&hA, &u.x, 4); memcpy(&hB, &u.y, 4);
                float2 fa = __half22float2(hA);
                float2 fb = __half22float2(hB);
                S[j][0] += fa.x; S[j][1] += fa.y;
                S[j][2] += fb.x; S[j][3] += fb.y;
            }
        }

        // ---- online softmax (rows rA = lane/4, rB = rA+8) ----
        float tmA = -INFINITY, tmB = -INFINITY;
        #pragma unroll
        for (int j = 0; j < 8; ++j) {
            tmA = fmaxf(tmA, fmaxf(S[j][0], S[j][1]));
            tmB = fmaxf(tmB, fmaxf(S[j][2], S[j][3]));
        }
        tmA = fmaxf(tmA, __shfl_xor_sync(0xffffffffu, tmA, 1));
        tmA = fmaxf(tmA, __shfl_xor_sync(0xffffffffu, tmA, 2));
        tmB = fmaxf(tmB, __shfl_xor_sync(0xffffffffu, tmB, 1));
        tmB = fmaxf(tmB, __shfl_xor_sync(0xffffffffu, tmB, 2));
        float mnA = fmaxf(mA, tmA), mnB = fmaxf(mB, tmB);
        float capA = __expf(mA - mnA), capB = __expf(mB - mnB);
        mA = mnA; mB = mnB;
        lA *= capA; lB *= capB;
        #pragma unroll
        for (int j = 0; j < 4; ++j) {
            O[j][0] *= capA; O[j][1] *= capA;
            O[j][2] *= capB; O[j][3] *= capB;
        }

        // ---- exp -> split fp16 P fragments ----
        u32 Ph[4][4], Pl[4][4];
        float sumA = 0.f, sumB = 0.f;
        #pragma unroll
        for (int j = 0; j < 8; ++j) {
            float p0 = __expf(S[j][0] - mA), p1 = __expf(S[j][1] - mA);
            float p2 = __expf(S[j][2] - mB), p3 = __expf(S[j][3] - mB);
            sumA += p0 + p1; sumB += p2 + p3;
            __half2 h01 = __floats2half2_rn(p0, p1);
            __half2 h23 = __floats2half2_rn(p2, p3);
            float2 r01 = __half22float2(h01);
            float2 r23 = __half22float2(h23);
            __half2 e01 = __floats2half2_rn(p0 - r01.x, p1 - r01.y);
            __half2 e23 = __floats2half2_rn(p2 - r23.x, p3 - r23.y);
            int g = j >> 1, ix = (j & 1) * 2;
            Ph[g][ix] = h2u(h01); Ph[g][ix + 1] = h2u(h23);
            Pl[g][ix] = h2u(e01); Pl[g][ix + 1] = h2u(e23);
        }
        lA += sumA; lB += sumB;

        // ---- P @ V ----
        #pragma unroll
        for (int g = 0; g < 4; ++g) {
            u32 v0[4], v1[4];
            LDSM4T(v0, sptr(&sV[buf][16 * g + rV][cV]));
            LDSM4T(v1, sptr(&sV[buf][16 * g + rV][16 + cV]));
            MMA(O[0], Ph[g], v0[0], v0[1]); MMA(O[1], Ph[g], v0[2], v0[3]);
            MMA(O[2], Ph[g], v1[0], v1[1]); MMA(O[3], Ph[g], v1[2], v1[3]);
            MMA(O[0], Pl[g], v0[0], v0[1]); MMA(O[1], Pl[g], v0[2], v0[3]);
            MMA(O[2], Pl[g], v1[0], v1[1]); MMA(O[3], Pl[g], v1[2], v1[3]);
        }
        __syncthreads();
    }

    // ---- epilogue: quad-reduce l, normalize, write ----
    lA += __shfl_xor_sync(0xffffffffu, lA, 1);
    lA += __shfl_xor_sync(0xffffffffu, lA, 2);
    lB += __shfl_xor_sync(0xffffffffu, lB, 1);
    lB += __shfl_xor_sync(0xffffffffu, lB, 2);
    float iA = 1.f / lA, iB = 1.f / lB;
    int rA = qbw + (lane >> 2), rB = rA + 8;
    int cb = h * DHn + 2 * (lane & 3);
    #pragma unroll
    for (int j = 0; j < 4; ++j) {
        float2 oa = { O[j][0] * iA, O[j][1] * iA };
        float2 ob = { O[j][2] * iB, O[j][3] * iB };
        *(float2*)&out[(size_t)(b * Nn + rA) * On + cb + 8 * j] = oa;
        *(float2*)&out[(size_t)(b * Nn + rB) * On + cb + 8 * j] = ob;
    }
}

// ================= launch =================
extern "C" void kernel_launch(void* const* d_in, const int* in_sizes, int n_in,
                              void* d_out, int out_size)
{
    const float* x         = (const float*)d_in[0];
    const float* adj       = (const float*)d_in[1];
    const float* edge_attr = (const float*)d_in[2];
    const float* qkv_w     = (const float*)d_in[3];
    const float* qkv_b     = (const float*)d_in[4];
    const float* e_w1      = (const float*)d_in[5];
    const float* e_b1      = (const float*)d_in[6];
    const float* e_w2      = (const float*)d_in[7];
    const float* e_b2      = (const float*)d_in[8];
    const float* shifts    = (const float*)d_in[9];
    const float* widths    = (const float*)d_in[10];
    const float* slW       = (const float*)d_in[11];
    const int*   edge_idx  = (const int*)d_in[12];
    float*       out       = (float*)d_out;

    // bias first so the fused edge kernel can RMW into it
    bias_kernel<<<(Bn * Nn * (Nn / 8)) / 256, 256>>>(adj, shifts, widths, slW);
    convert_kernel<<<(Bn * Nn * DINn + DINn * 768 + 255) / 256, 256>>>(x, qkv_w);
    qkv_mma_kernel<<<dim3(768 / 64, (Bn * Nn) / 64), 128>>>(qkv_b);
    edge_fused_kernel<<<(Bn * En) / 256, 256>>>(edge_attr, e_w1, e_b1, e_w2, e_b2, edge_idx);
    attn_kernel<<<dim3(Nn / 64, Hn, Bn), 128>>>(out);
}

// round 13
// speedup vs baseline: 3.1952x; 1.0264x over previous
#include <cuda_runtime.h>
#include <cuda_fp16.h>
#include <math.h>
#include <stdint.h>

#define Bn   2
#define Nn   2048
#define Hn   8
#define DHn  32
#define En   65536
#define DINn 256
#define On   256
#define INVSCALE 0.17677669529663687f
#define LOGCLIP  -13.815510557964274f

#define KT 64
#define NTILES (Nn / KT)

typedef uint32_t u32;

// -------- static device scratch --------
__device__ __half g_Qh[(size_t)Bn * Hn * Nn * DHn];
__device__ __half g_Ql[(size_t)Bn * Hn * Nn * DHn];
__device__ __half g_Kh[(size_t)Bn * Hn * Nn * DHn];
__device__ __half g_Kl[(size_t)Bn * Hn * Nn * DHn];
__device__ __half g_Vh[(size_t)Bn * Hn * Nn * DHn];
__device__ float  g_ea[(size_t)Bn * En * Hn];   // [b][e][h] (coalesced for scatter)
// fragment-interleaved bias: [b][h][q>>4][k>>3][lane 0..31][4 halfs]
__device__ __half g_bias[(size_t)Bn * Hn * Nn * Nn];
// split-fp16 copies of x and qkv_w for the tensor-core projection
__device__ __half g_xh[(size_t)Bn * Nn * DINn];
__device__ __half g_xl[(size_t)Bn * Nn * DINn];
__device__ __half g_wh[(size_t)DINn * 768];
__device__ __half g_wl[(size_t)DINn * 768];

#define CP_ASYNC16(smem_u32, gptr) \
    asm volatile("cp.async.cg.shared.global [%0], [%1], 16;" :: "r"(smem_u32), "l"(gptr))
#define CP_COMMIT() asm volatile("cp.async.commit_group;")
#define CP_WAIT1()  asm volatile("cp.async.wait_group 1;")
#define CP_WAIT0()  asm volatile("cp.async.wait_group 0;")

__device__ __forceinline__ u32 sptr(const void* p) {
    return (u32)__cvta_generic_to_shared(p);
}
#define LDSM4(r, addr) \
    asm volatile("ldmatrix.sync.aligned.m8n8.x4.shared.b16 {%0,%1,%2,%3}, [%4];" \
        : "=r"(r[0]), "=r"(r[1]), "=r"(r[2]), "=r"(r[3]) : "r"(addr))
#define LDSM4T(r, addr) \
    asm volatile("ldmatrix.sync.aligned.m8n8.x4.trans.shared.b16 {%0,%1,%2,%3}, [%4];" \
        : "=r"(r[0]), "=r"(r[1]), "=r"(r[2]), "=r"(r[3]) : "r"(addr))
#define MMA(c, a, b0, b1) \
    asm volatile("mma.sync.aligned.m16n8k16.row.col.f32.f16.f16.f32 " \
        "{%0,%1,%2,%3},{%4,%5,%6,%7},{%8,%9},{%0,%1,%2,%3};" \
        : "+f"(c[0]), "+f"(c[1]), "+f"(c[2]), "+f"(c[3]) \
        : "r"(a[0]), "r"(a[1]), "r"(a[2]), "r"(a[3]), "r"(b0), "r"(b1))

__device__ __forceinline__ u32 h2u(__half2 h) { u32 r; memcpy(&r, &h, 4); return r; }

// ================= fp32 -> split fp16 conversion (x and w) =================
__global__ __launch_bounds__(256) void convert_kernel(
    const float* __restrict__ x, const float* __restrict__ w)
{
    int i = blockIdx.x * 256 + threadIdx.x;
    const int NX = Bn * Nn * DINn;          // 1048576
    if (i < NX) {
        float v = x[i];
        __half hi = __float2half_rn(v);
        g_xh[i] = hi;
        g_xl[i] = __float2half_rn(v - __half2float(hi));
    } else {
        int j = i - NX;
        if (j < DINn * 768) {
            float v = w[j];
            __half hi = __float2half_rn(v);
            g_wh[j] = hi;
            g_wl[j] = __float2half_rn(v - __half2float(hi));
        }
    }
}

// ================= QKV projection: split-fp16 tensor-core GEMM ==============
#define QK_PADX 40
#define QK_PADW 72
__global__ __launch_bounds__(128) void qkv_mma_kernel(const float* __restrict__ bias)
{
    __shared__ __align__(16) __half sXh[2][64][QK_PADX];
    __shared__ __align__(16) __half sXl[2][64][QK_PADX];
    __shared__ __align__(16) __half sWh[2][32][QK_PADW];
    __shared__ __align__(16) __half sWl[2][32][QK_PADW];

    const int tid = threadIdx.x, warp = tid >> 5, lane = tid & 31;
    const int row0 = blockIdx.y * 64;
    const int col0 = blockIdx.x * 64;

    auto load_tile = [&](int buf, int k0) {
        #pragma unroll
        for (int m = 0; m < 2; ++m) {
            int i = tid + m * 128;
            int r = i >> 2, c = (i & 3) * 8;
            const __half* s = g_xh + (size_t)(row0 + r) * DINn + k0 + c;
            CP_ASYNC16(sptr(&sXh[buf][r][c]), s);
            s = g_xl + (size_t)(row0 + r) * DINn + k0 + c;
            CP_ASYNC16(sptr(&sXl[buf][r][c]), s);
        }
        #pragma unroll
        for (int m = 0; m < 2; ++m) {
            int i = tid + m * 128;
            int r = i >> 3, c = (i & 7) * 8;
            const __half* s = g_wh + (size_t)(k0 + r) * 768 + col0 + c;
            CP_ASYNC16(sptr(&sWh[buf][r][c]), s);
            s = g_wl + (size_t)(k0 + r) * 768 + col0 + c;
            CP_ASYNC16(sptr(&sWl[buf][r][c]), s);
        }
    };

    load_tile(0, 0);
    CP_COMMIT();

    float C[8][4];
    #pragma unroll
    for (int j = 0; j < 8; ++j)
        #pragma unroll
        for (int i = 0; i < 4; ++i) C[j][i] = 0.f;

    const int rA = warp * 16 + (lane & 15);
    const int cA = (lane >> 4) * 8;
    const int rB = (lane & 7) + ((lane >> 3) & 1) * 8;
    const int cB = (lane >> 4) * 8;

    for (int kc = 0; kc < 8; ++kc) {
        if (kc + 1 < 8) { load_tile((kc + 1) & 1, (kc + 1) * 32); CP_COMMIT(); CP_WAIT1(); }
        else { CP_WAIT0(); }
        __syncthreads();
        const int buf = kc & 1;

        #pragma unroll
        for (int ks = 0; ks < 2; ++ks) {
            const int ko = ks * 16;
            u32 ah[4], al[4];
            LDSM4(ah, sptr(&sXh[buf][rA][ko + cA]));
            LDSM4(al, sptr(&sXl[buf][rA][ko + cA]));
            #pragma unroll
            for (int g = 0; g < 4; ++g) {
                u32 wh[4], wl[4];
                LDSM4T(wh, sptr(&sWh[buf][ko + rB][g * 16 + cB]));
                LDSM4T(wl, sptr(&sWl[buf][ko + rB][g * 16 + cB]));
                MMA(C[2 * g],     ah, wh[0], wh[1]);
                MMA(C[2 * g + 1], ah, wh[2], wh[3]);
                MMA(C[2 * g],     al, wh[0], wh[1]);
                MMA(C[2 * g + 1], al, wh[2], wh[3]);
                MMA(C[2 * g],     ah, wl[0], wl[1]);
                MMA(C[2 * g + 1], ah, wl[2], wl[3]);
            }
        }
        __syncthreads();
    }

    #pragma unroll
    for (int j = 0; j < 8; ++j) {
        #pragma unroll
        for (int i = 0; i < 4; ++i) {
            int row = row0 + warp * 16 + (lane >> 2) + (i >> 1) * 8;
            int col = col0 + j * 8 + 2 * (lane & 3) + (i & 1);
            float v = C[j][i] + __ldg(bias + col);
            int bb = row >> 11, n = row & (Nn - 1);
            int s = col >> 8, hh = (col >> 5) & 7, d = col & 31;
            size_t idx = (((size_t)(bb * Hn + hh)) * Nn + n) * DHn + d;
            if (s == 0) {
                float vq = v * INVSCALE;
                __half hi = __float2half_rn(vq);
                g_Qh[idx] = hi;
                g_Ql[idx] = __float2half_rn(vq - __half2float(hi));
            } else if (s == 1) {
                __half hi = __float2half_rn(v);
                g_Kh[idx] = hi;
                g_Kl[idx] = __float2half_rn(v - __half2float(hi));
            } else {
                g_Vh[idx] = __float2half_rn(v);
            }
        }
    }
}

// ====== dense bias (moire + self-loop), coalesced 32B stores ======
// Thread owns fragment rows q and q+8 of one (qblk, k8) chunk: the 16 halfs
// covering {q,q+8} x {8 k} are CONTIGUOUS in the interleaved layout ->
// two uint4 stores. qlow is the fastest index so a warp writes 1KB runs.
__global__ __launch_bounds__(256) void bias_kernel(
    const float* __restrict__ adj,
    const float* __restrict__ shifts, const float* __restrict__ widths,
    const float* __restrict__ slW)
{
    int idx = blockIdx.x * 256 + threadIdx.x;   // B * 128 * 256 * 8 = 524288
    int qlow = idx & 7;
    int k8   = (idx >> 3) & 255;
    int qblk = (idx >> 11) & 127;
    int b    = idx >> 18;

    int q0 = qblk * 16 + qlow;       // row with qhi bit 0
    int q1 = q0 + 8;                 // row with qhi bit 1
    int kbase = k8 * 8;

    const float* ap0 = adj + ((size_t)b * Nn + q0) * Nn + kbase;
    const float* ap1 = adj + ((size_t)b * Nn + q1) * Nn + kbase;
    float4 x0 = *(const float4*)ap0, x1 = *(const float4*)(ap0 + 4);
    float4 y0 = *(const float4*)ap1, y1 = *(const float4*)(ap1 + 4);
    float a0[8] = {x0.x, x0.y, x0.z, x0.w, x1.x, x1.y, x1.z, x1.w};
    float a1[8] = {y0.x, y0.y, y0.z, y0.w, y1.x, y1.y, y1.z, y1.w};
    int d0 = q0 - kbase;   // self-loop col for row q0 if in [0,8)
    int d1 = q1 - kbase;

    #pragma unroll
    for (int h = 0; h < 8; ++h) {
        float sh = __ldg(shifts + h);
        float wd = __ldg(widths + h);
        float inv2w2 = 1.f / (2.f * wd * wd);
        float sl = __ldg(slW + h);

        float z0[8], z1[8];
        #pragma unroll
        for (int i = 0; i < 8; ++i) {
            float t0 = a0[i] - sh;
            float t1 = a1[i] - sh;
            z0[i] = fmaxf(-t0 * t0 * inv2w2, LOGCLIP);
            z1[i] = fmaxf(-t1 * t1 * inv2w2, LOGCLIP);
            if (i == d0) z0[i] += sl;
            if (i == d1) z1[i] += sl;
        }
        // halfs [qlow*16 .. +15]: [q k0,q k1, q8 k0,q8 k1, q k2,q k3, q8 k2,q8 k3, ...]
        __half* dst = g_bias +
            ((((size_t)(b * 8 + h)) * 128 + qblk) * 256 + k8) * 128 + qlow * 16;
        __half2 p0 = __floats2half2_rn(z0[0], z0[1]);
        __half2 p1 = __floats2half2_rn(z1[0], z1[1]);
        __half2 p2 = __floats2half2_rn(z0[2], z0[3]);
        __half2 p3 = __floats2half2_rn(z1[2], z1[3]);
        __half2 p4 = __floats2half2_rn(z0[4], z0[5]);
        __half2 p5 = __floats2half2_rn(z1[4], z1[5]);
        __half2 p6 = __floats2half2_rn(z0[6], z0[7]);
        __half2 p7 = __floats2half2_rn(z1[6], z1[7]);
        uint4 w0 = { h2u(p0), h2u(p1), h2u(p2), h2u(p3) };
        uint4 w1 = { h2u(p4), h2u(p5), h2u(p6), h2u(p7) };
        *(uint4*)dst = w0;
        *(uint4*)(dst + 8) = w1;
    }
}

// ================= edge FFN (1 thread/edge, [b][e][h] output) ===============
__global__ __launch_bounds__(256) void edge_ffn_kernel(
    const float* __restrict__ edge_attr,
    const float* __restrict__ e_w1, const float* __restrict__ e_b1,
    const float* __restrict__ e_w2, const float* __restrict__ e_b2)
{
    __shared__ float w1s[64], w2s[64], b1s[8], b2s[8];
    int tid = threadIdx.x;
    if (tid < 64) { w1s[tid] = e_w1[tid]; w2s[tid] = e_w2[tid]; }
    if (tid < 8)  { b1s[tid] = e_b1[tid]; b2s[tid] = e_b2[tid]; }
    __syncthreads();

    int gid = blockIdx.x * 256 + tid;   // < B*E
    float cur[8];
    const float* ap = edge_attr + (size_t)gid * Hn;
    #pragma unroll
    for (int i = 0; i < 8; ++i) cur[i] = ap[i];

    #pragma unroll
    for (int pass = 0; pass < 2; ++pass) {
        float t1[8], t2[8];
        #pragma unroll
        for (int j = 0; j < 8; ++j) {
            float s = b1s[j];
            #pragma unroll
            for (int i = 0; i < 8; ++i) s = fmaf(cur[i], w1s[i * 8 + j], s);
            t1[j] = fmaxf(s, 0.f);
        }
        #pragma unroll
        for (int j = 0; j < 8; ++j) {
            float s = b2s[j];
            #pragma unroll
            for (int i = 0; i < 8; ++i) s = fmaf(t1[i], w2s[i * 8 + j], s);
            t2[j] = s;
        }
        #pragma unroll
        for (int j = 0; j < 8; ++j) cur[j] = t2[j];
    }
    float* dst = g_ea + (size_t)gid * Hn;
    #pragma unroll
    for (int h = 0; h < 8; ++h) dst[h] = cur[h];
}

// ====== scatter: 1 thread per (edge, h); tiny regs, max latency hiding ======
// (b,u,v) unique per batch -> per-h addresses unique -> plain RMW is safe.
// MUST run after bias_kernel and edge_ffn_kernel.
__global__ __launch_bounds__(256) void edge_scatter_kernel(
    const int* __restrict__ edge_index)
{
    int gid = blockIdx.x * 256 + threadIdx.x;   // < B*E*8
    int h = gid & 7;
    int e = (gid >> 3) & (En - 1);
    int b = gid >> 19;

    int u = __ldg(edge_index + (size_t)b * 2 * En + e);
    int v = __ldg(edge_index + (size_t)b * 2 * En + En + e);
    float ea = g_ea[(size_t)(b * En + e) * Hn + h];

    size_t inoff = (size_t)(((u & 7) * 4 + ((v & 7) >> 1)) * 4 + ((u >> 3) & 1) * 2 + (v & 1));
    size_t a = ((((size_t)(b * 8 + h)) * 128 + (u >> 4)) * 256 + (v >> 3)) * 128 + inoff;
    g_bias[a] = __float2half_rn(__half2float(g_bias[a]) + ea);
}

// ================= tensor-core attention =================
__global__ __launch_bounds__(128) void attn_kernel(float* __restrict__ out)
{
    __shared__ __align__(16) __half sKh[2][64][40];
    __shared__ __align__(16) __half sKl[2][64][40];
    __shared__ __align__(16) __half sV [2][64][40];
    __shared__ __align__(16) __half sQh[64][40];
    __shared__ __align__(16) __half sQl[64][40];

    const int b = blockIdx.z, h = blockIdx.y;
    const int tid = threadIdx.x, warp = tid >> 5, lane = tid & 31;
    const int qb0 = blockIdx.x * 64;
    const int qbw = qb0 + warp * 16;

    const size_t plane = ((size_t)(b * Hn + h)) * Nn * DHn;
    const __half* gKh = g_Kh + plane;
    const __half* gKl = g_Kl + plane;
    const __half* gV  = g_Vh + plane;
    const __half* gB  = g_bias +
        ((((size_t)(b * Hn + h)) * 128 + (qbw >> 4)) * 256) * 128 + lane * 4;

    auto load_tile = [&](int buf, int t) {
        #pragma unroll
        for (int m = 0; m < 2; ++m) {
            int i = tid + m * 128;
            int row = i >> 2, c = (i & 3) * 8;
            const __half* s;
            s = gKh + (size_t)t * KT * DHn + row * DHn + c;
            CP_ASYNC16(sptr(&sKh[buf][row][c]), s);
            s = gKl + (size_t)t * KT * DHn + row * DHn + c;
            CP_ASYNC16(sptr(&sKl[buf][row][c]), s);
            s = gV + (size_t)t * KT * DHn + row * DHn + c;
            CP_ASYNC16(sptr(&sV[buf][row][c]), s);
        }
    };

    load_tile(0, 0);
    CP_COMMIT();

    {
        const __half* gqh = g_Qh + plane + (size_t)qb0 * DHn;
        const __half* gql = g_Ql + plane + (size_t)qb0 * DHn;
        for (int i = tid; i < 256; i += 128) {
            int row = i >> 2, c = (i & 3) * 8;
            *(uint4*)&sQh[row][c] = *(const uint4*)(gqh + row * DHn + c);
            *(uint4*)&sQl[row][c] = *(const uint4*)(gql + row * DHn + c);
        }
    }
    __syncthreads();

    u32 qh[2][4], ql[2][4];
    {
        int rowQ = warp * 16 + (lane & 7) + ((lane >> 3) & 1) * 8;
        int colQ = (lane >> 4) * 8;
        #pragma unroll
        for (int t = 0; t < 2; ++t) {
            LDSM4(qh[t], sptr(&sQh[rowQ][t * 16 + colQ]));
            LDSM4(ql[t], sptr(&sQl[rowQ][t * 16 + colQ]));
        }
    }

    const int rK = (lane & 7) + ((lane >> 4) & 1) * 8;
    const int cK = ((lane >> 3) & 1) * 8;
    const int rV = (lane & 7) + ((lane >> 3) & 1) * 8;
    const int cV = (lane >> 4) * 8;

    float O[4][4] = {};
    float mA = -INFINITY, mB = -INFINITY, lA = 0.f, lB = 0.f;

    for (int t = 0; t < NTILES; ++t) {
        if (t + 1 < NTILES) { load_tile((t + 1) & 1, t + 1); CP_COMMIT(); CP_WAIT1(); }
        else { CP_WAIT0(); }
        __syncthreads();
        const int buf = t & 1;

        float S[8][4];
        #pragma unroll
        for (int j = 0; j < 8; ++j)
            #pragma unroll
            for (int i = 0; i < 4; ++i) S[j][i] = 0.f;

        #pragma unroll
        for (int g = 0; g < 4; ++g) {
            u32 kh0[4], kh1[4], kl0[4], kl1[4];
            LDSM4(kh0, sptr(&sKh[buf][16 * g + rK][cK]));
            LDSM4(kh1, sptr(&sKh[buf][16 * g + rK][16 + cK]));
            LDSM4(kl0, sptr(&sKl[buf][16 * g + rK][cK]));
            LDSM4(kl1, sptr(&sKl[buf][16 * g + rK][16 + cK]));
            float* s0 = S[2 * g];
            float* s1 = S[2 * g + 1];
            MMA(s0, qh[0], kh0[0], kh0[1]); MMA(s0, qh[1], kh1[0], kh1[1]);
            MMA(s0, ql[0], kh0[0], kh0[1]); MMA(s0, ql[1], kh1[0], kh1[1]);
            MMA(s0, qh[0], kl0[0], kl0[1]); MMA(s0, qh[1], kl1[0], kl1[1]);
            MMA(s1, qh[0], kh0[2], kh0[3]); MMA(s1, qh[1], kh1[2], kh1[3]);
            MMA(s1, ql[0], kh0[2], kh0[3]); MMA(s1, ql[1], kh1[2], kh1[3]);
            MMA(s1, qh[0], kl0[2], kl0[3]); MMA(s1, qh[1], kl1[2], kl1[3]);
        }

        {
            const __half* bp = gB + (size_t)(t * 8) * 128;
            #pragma unroll
            for (int j = 0; j < 8; ++j) {
                uint2 u = *(const uint2*)(bp + (size_t)j * 128);
                __half2 hA, hB; memcpy(&hA, &u.x, 4); memcpy(&hB, &u.y, 4);
                float2 fa = __half22float2(hA);
                float2 fb = __half22float2(hB);
                S[j][0] += fa.x; S[j][1] += fa.y;
                S[j][2] += fb.x; S[j][3] += fb.y;
            }
        }

        float tmA = -INFINITY, tmB = -INFINITY;
        #pragma unroll
        for (int j = 0; j < 8; ++j) {
            tmA = fmaxf(tmA, fmaxf(S[j][0], S[j][1]));
            tmB = fmaxf(tmB, fmaxf(S[j][2], S[j][3]));
        }
        tmA = fmaxf(tmA, __shfl_xor_sync(0xffffffffu, tmA, 1));
        tmA = fmaxf(tmA, __shfl_xor_sync(0xffffffffu, tmA, 2));
        tmB = fmaxf(tmB, __shfl_xor_sync(0xffffffffu, tmB, 1));
        tmB = fmaxf(tmB, __shfl_xor_sync(0xffffffffu, tmB, 2));
        float mnA = fmaxf(mA, tmA), mnB = fmaxf(mB, tmB);
        float capA = __expf(mA - mnA), capB = __expf(mB - mnB);
        mA = mnA; mB = mnB;
        lA *= capA; lB *= capB;
        #pragma unroll
        for (int j = 0; j < 4; ++j) {
            O[j][0] *= capA; O[j][1] *= capA;
            O[j][2] *= capB; O[j][3] *= capB;
        }

        u32 Ph[4][4], Pl[4][4];
        float sumA = 0.f, sumB = 0.f;
        #pragma unroll
        for (int j = 0; j < 8; ++j) {
            float p0 = __expf(S[j][0] - mA), p1 = __expf(S[j][1] - mA);
            float p2 = __expf(S[j][2] - mB), p3 = __expf(S[j][3] - mB);
            sumA += p0 + p1; sumB += p2 + p3;
            __half2 h01 = __floats2half2_rn(p0, p1);
            __half2 h23 = __floats2half2_rn(p2, p3);
            float2 r01 = __half22float2(h01);
            float2 r23 = __half22float2(h23);
            __half2 e01 = __floats2half2_rn(p0 - r01.x, p1 - r01.y);
            __half2 e23 = __floats2half2_rn(p2 - r23.x, p3 - r23.y);
            int g = j >> 1, ix = (j & 1) * 2;
            Ph[g][ix] = h2u(h01); Ph[g][ix + 1] = h2u(h23);
            Pl[g][ix] = h2u(e01); Pl[g][ix + 1] = h2u(e23);
        }
        lA += sumA; lB += sumB;

        #pragma unroll
        for (int g = 0; g < 4; ++g) {
            u32 v0[4], v1[4];
            LDSM4T(v0, sptr(&sV[buf][16 * g + rV][cV]));
            LDSM4T(v1, sptr(&sV[buf][16 * g + rV][16 + cV]));
            MMA(O[0], Ph[g], v0[0], v0[1]); MMA(O[1], Ph[g], v0[2], v0[3]);
            MMA(O[2], Ph[g], v1[0], v1[1]); MMA(O[3], Ph[g], v1[2], v1[3]);
            MMA(O[0], Pl[g], v0[0], v0[1]); MMA(O[1], Pl[g], v0[2], v0[3]);
            MMA(O[2], Pl[g], v1[0], v1[1]); MMA(O[3], Pl[g], v1[2], v1[3]);
        }
        __syncthreads();
    }

    lA += __shfl_xor_sync(0xffffffffu, lA, 1);
    lA += __shfl_xor_sync(0xffffffffu, lA, 2);
    lB += __shfl_xor_sync(0xffffffffu, lB, 1);
    lB += __shfl_xor_sync(0xffffffffu, lB, 2);
    float iA = 1.f / lA, iB = 1.f / lB;
    int rA = qbw + (lane >> 2), rB = rA + 8;
    int cb = h * DHn + 2 * (lane & 3);
    #pragma unroll
    for (int j = 0; j < 4; ++j) {
        float2 oa = { O[j][0] * iA, O[j][1] * iA };
        float2 ob = { O[j][2] * iB, O[j][3] * iB };
        *(float2*)&out[(size_t)(b * Nn + rA) * On + cb + 8 * j] = oa;
        *(float2*)&out[(size_t)(b * Nn + rB) * On + cb + 8 * j] = ob;
    }
}

// ================= launch =================
extern "C" void kernel_launch(void* const* d_in, const int* in_sizes, int n_in,
                              void* d_out, int out_size)
{
    const float* x         = (const float*)d_in[0];
    const float* adj       = (const float*)d_in[1];
    const float* edge_attr = (const float*)d_in[2];
    const float* qkv_w     = (const float*)d_in[3];
    const float* qkv_b     = (const float*)d_in[4];
    const float* e_w1      = (const float*)d_in[5];
    const float* e_b1      = (const float*)d_in[6];
    const float* e_w2      = (const float*)d_in[7];
    const float* e_b2      = (const float*)d_in[8];
    const float* shifts    = (const float*)d_in[9];
    const float* widths    = (const float*)d_in[10];
    const float* slW       = (const float*)d_in[11];
    const int*   edge_idx  = (const int*)d_in[12];
    float*       out       = (float*)d_out;

    edge_ffn_kernel<<<(Bn * En) / 256, 256>>>(edge_attr, e_w1, e_b1, e_w2, e_b2);
    bias_kernel<<<(Bn * 128 * 256 * 8) / 256, 256>>>(adj, shifts, widths, slW);
    convert_kernel<<<(Bn * Nn * DINn + DINn * 768 + 255) / 256, 256>>>(x, qkv_w);
    qkv_mma_kernel<<<dim3(768 / 64, (Bn * Nn) / 64), 128>>>(qkv_b);
    edge_scatter_kernel<<<(Bn * En * Hn) / 256, 256>>>(edge_idx);
    attn_kernel<<<dim3(Nn / 64, Hn, Bn), 128>>>(out);
}

// round 15
// speedup vs baseline: 3.4222x; 1.0711x over previous
#include <cuda_runtime.h>
#include <cuda_fp16.h>
#include <math.h>
#include <stdint.h>

#define Bn   2
#define Nn   2048
#define Hn   8
#define DHn  32
#define En   65536
#define DINn 256
#define On   256
#define INVSCALE 0.17677669529663687f
#define LOGCLIP  -13.815510557964274f

#define KT 64
#define NTILES (Nn / KT)

typedef uint32_t u32;

// -------- static device scratch --------
__device__ __half g_Qh[(size_t)Bn * Hn * Nn * DHn];
__device__ __half g_Ql[(size_t)Bn * Hn * Nn * DHn];
__device__ __half g_Kh[(size_t)Bn * Hn * Nn * DHn];
__device__ __half g_Kl[(size_t)Bn * Hn * Nn * DHn];
__device__ __half g_Vh[(size_t)Bn * Hn * Nn * DHn];
__device__ float  g_ea[(size_t)Bn * En * Hn];   // [b][e][h] (coalesced for scatter)
// fragment-interleaved bias: [b][h][q>>4][k>>3][lane 0..31][4 halfs]
__device__ __half g_bias[(size_t)Bn * Hn * Nn * Nn];
// split-fp16 copies of x and qkv_w for the tensor-core projection
__device__ __half g_xh[(size_t)Bn * Nn * DINn];
__device__ __half g_xl[(size_t)Bn * Nn * DINn];
__device__ __half g_wh[(size_t)DINn * 768];
__device__ __half g_wl[(size_t)DINn * 768];

#define CP_ASYNC16(smem_u32, gptr) \
    asm volatile("cp.async.cg.shared.global [%0], [%1], 16;" :: "r"(smem_u32), "l"(gptr))
#define CP_COMMIT() asm volatile("cp.async.commit_group;")
#define CP_WAIT1()  asm volatile("cp.async.wait_group 1;")
#define CP_WAIT0()  asm volatile("cp.async.wait_group 0;")

__device__ __forceinline__ u32 sptr(const void* p) {
    return (u32)__cvta_generic_to_shared(p);
}
#define LDSM4(r, addr) \
    asm volatile("ldmatrix.sync.aligned.m8n8.x4.shared.b16 {%0,%1,%2,%3}, [%4];" \
        : "=r"(r[0]), "=r"(r[1]), "=r"(r[2]), "=r"(r[3]) : "r"(addr))
#define LDSM4T(r, addr) \
    asm volatile("ldmatrix.sync.aligned.m8n8.x4.trans.shared.b16 {%0,%1,%2,%3}, [%4];" \
        : "=r"(r[0]), "=r"(r[1]), "=r"(r[2]), "=r"(r[3]) : "r"(addr))
#define MMA(c, a, b0, b1) \
    asm volatile("mma.sync.aligned.m16n8k16.row.col.f32.f16.f16.f32 " \
        "{%0,%1,%2,%3},{%4,%5,%6,%7},{%8,%9},{%0,%1,%2,%3};" \
        : "+f"(c[0]), "+f"(c[1]), "+f"(c[2]), "+f"(c[3]) \
        : "r"(a[0]), "r"(a[1]), "r"(a[2]), "r"(a[3]), "r"(b0), "r"(b1))

__device__ __forceinline__ u32 h2u(__half2 h) { u32 r; memcpy(&r, &h, 4); return r; }

// ================= fp32 -> split fp16 conversion (x and w) =================
__global__ __launch_bounds__(256) void convert_kernel(
    const float* __restrict__ x, const float* __restrict__ w)
{
    int i = blockIdx.x * 256 + threadIdx.x;
    const int NX = Bn * Nn * DINn;          // 1048576
    if (i < NX) {
        float v = x[i];
        __half hi = __float2half_rn(v);
        g_xh[i] = hi;
        g_xl[i] = __float2half_rn(v - __half2float(hi));
    } else {
        int j = i - NX;
        if (j < DINn * 768) {
            float v = w[j];
            __half hi = __float2half_rn(v);
            g_wh[j] = hi;
            g_wl[j] = __float2half_rn(v - __half2float(hi));
        }
    }
}

// ================= QKV projection: split-fp16 tensor-core GEMM ==============
// Tile M=64, N=128 per CTA (128 thr) -> grid 6x64 = 384 CTAs = ONE wave.
#define QK_PADX 40
#define QK_PADW 136
__global__ __launch_bounds__(128, 3) void qkv_mma_kernel(const float* __restrict__ bias)
{
    __shared__ __align__(16) __half sXh[2][64][QK_PADX];
    __shared__ __align__(16) __half sXl[2][64][QK_PADX];
    __shared__ __align__(16) __half sWh[2][32][QK_PADW];
    __shared__ __align__(16) __half sWl[2][32][QK_PADW];

    const int tid = threadIdx.x, warp = tid >> 5, lane = tid & 31;
    const int row0 = blockIdx.y * 64;
    const int col0 = blockIdx.x * 128;

    auto load_tile = [&](int buf, int k0) {
        // X: 64 rows x 32 halfs (hi+lo): 256 16B-chunks each
        #pragma unroll
        for (int m = 0; m < 2; ++m) {
            int i = tid + m * 128;
            int r = i >> 2, c = (i & 3) * 8;
            const __half* s = g_xh + (size_t)(row0 + r) * DINn + k0 + c;
            CP_ASYNC16(sptr(&sXh[buf][r][c]), s);
            s = g_xl + (size_t)(row0 + r) * DINn + k0 + c;
            CP_ASYNC16(sptr(&sXl[buf][r][c]), s);
        }
        // W: 32 rows x 128 halfs (hi+lo): 512 16B-chunks each
        #pragma unroll
        for (int m = 0; m < 4; ++m) {
            int i = tid + m * 128;
            int r = i >> 4, c = (i & 15) * 8;
            const __half* s = g_wh + (size_t)(k0 + r) * 768 + col0 + c;
            CP_ASYNC16(sptr(&sWh[buf][r][c]), s);
            s = g_wl + (size_t)(k0 + r) * 768 + col0 + c;
            CP_ASYNC16(sptr(&sWl[buf][r][c]), s);
        }
    };

    load_tile(0, 0);
    CP_COMMIT();

    float C[16][4];
    #pragma unroll
    for (int j = 0; j < 16; ++j)
        #pragma unroll
        for (int i = 0; i < 4; ++i) C[j][i] = 0.f;

    const int rA = warp * 16 + (lane & 15);
    const int cA = (lane >> 4) * 8;
    const int rB = (lane & 7) + ((lane >> 3) & 1) * 8;
    const int cB = (lane >> 4) * 8;

    for (int kc = 0; kc < 8; ++kc) {
        if (kc + 1 < 8) { load_tile((kc + 1) & 1, (kc + 1) * 32); CP_COMMIT(); CP_WAIT1(); }
        else { CP_WAIT0(); }
        __syncthreads();
        const int buf = kc & 1;

        #pragma unroll
        for (int ks = 0; ks < 2; ++ks) {
            const int ko = ks * 16;
            u32 ah[4], al[4];
            LDSM4(ah, sptr(&sXh[buf][rA][ko + cA]));
            LDSM4(al, sptr(&sXl[buf][rA][ko + cA]));
            #pragma unroll
            for (int g = 0; g < 8; ++g) {
                u32 wh[4], wl[4];
                LDSM4T(wh, sptr(&sWh[buf][ko + rB][g * 16 + cB]));
                LDSM4T(wl, sptr(&sWl[buf][ko + rB][g * 16 + cB]));
                MMA(C[2 * g],     ah, wh[0], wh[1]);
                MMA(C[2 * g + 1], ah, wh[2], wh[3]);
                MMA(C[2 * g],     al, wh[0], wh[1]);
                MMA(C[2 * g + 1], al, wh[2], wh[3]);
                MMA(C[2 * g],     ah, wl[0], wl[1]);
                MMA(C[2 * g + 1], ah, wl[2], wl[3]);
            }
        }
        __syncthreads();
    }

    #pragma unroll
    for (int j = 0; j < 16; ++j) {
        #pragma unroll
        for (int i = 0; i < 4; ++i) {
            int row = row0 + warp * 16 + (lane >> 2) + (i >> 1) * 8;
            int col = col0 + j * 8 + 2 * (lane & 3) + (i & 1);
            float v = C[j][i] + __ldg(bias + col);
            int bb = row >> 11, n = row & (Nn - 1);
            int s = col >> 8, hh = (col >> 5) & 7, d = col & 31;
            size_t idx = (((size_t)(bb * Hn + hh)) * Nn + n) * DHn + d;
            if (s == 0) {
                float vq = v * INVSCALE;
                __half hi = __float2half_rn(vq);
                g_Qh[idx] = hi;
                g_Ql[idx] = __float2half_rn(vq - __half2float(hi));
            } else if (s == 1) {
                __half hi = __float2half_rn(v);
                g_Kh[idx] = hi;
                g_Kl[idx] = __float2half_rn(v - __half2float(hi));
            } else {
                g_Vh[idx] = __float2half_rn(v);
            }
        }
    }
}

// ====== dense bias (moire + self-loop), coalesced 32B stores ======
__global__ __launch_bounds__(256) void bias_kernel(
    const float* __restrict__ adj,
    const float* __restrict__ shifts, const float* __restrict__ widths,
    const float* __restrict__ slW)
{
    int idx = blockIdx.x * 256 + threadIdx.x;   // B * 128 * 256 * 8 = 524288
    int qlow = idx & 7;
    int k8   = (idx >> 3) & 255;
    int qblk = (idx >> 11) & 127;
    int b    = idx >> 18;

    int q0 = qblk * 16 + qlow;
    int q1 = q0 + 8;
    int kbase = k8 * 8;

    const float* ap0 = adj + ((size_t)b * Nn + q0) * Nn + kbase;
    const float* ap1 = adj + ((size_t)b * Nn + q1) * Nn + kbase;
    float4 x0 = *(const float4*)ap0, x1 = *(const float4*)(ap0 + 4);
    float4 y0 = *(const float4*)ap1, y1 = *(const float4*)(ap1 + 4);
    float a0[8] = {x0.x, x0.y, x0.z, x0.w, x1.x, x1.y, x1.z, x1.w};
    float a1[8] = {y0.x, y0.y, y0.z, y0.w, y1.x, y1.y, y1.z, y1.w};
    int d0 = q0 - kbase;
    int d1 = q1 - kbase;

    #pragma unroll
    for (int h = 0; h < 8; ++h) {
        float sh = __ldg(shifts + h);
        float wd = __ldg(widths + h);
        float inv2w2 = 1.f / (2.f * wd * wd);
        float sl = __ldg(slW + h);

        float z0[8], z1[8];
        #pragma unroll
        for (int i = 0; i < 8; ++i) {
            float t0 = a0[i] - sh;
            float t1 = a1[i] - sh;
            z0[i] = fmaxf(-t0 * t0 * inv2w2, LOGCLIP);
            z1[i] = fmaxf(-t1 * t1 * inv2w2, LOGCLIP);
            if (i == d0) z0[i] += sl;
            if (i == d1) z1[i] += sl;
        }
        __half* dst = g_bias +
            ((((size_t)(b * 8 + h)) * 128 + qblk) * 256 + k8) * 128 + qlow * 16;
        __half2 p0 = __floats2half2_rn(z0[0], z0[1]);
        __half2 p1 = __floats2half2_rn(z1[0], z1[1]);
        __half2 p2 = __floats2half2_rn(z0[2], z0[3]);
        __half2 p3 = __floats2half2_rn(z1[2], z1[3]);
        __half2 p4 = __floats2half2_rn(z0[4], z0[5]);
        __half2 p5 = __floats2half2_rn(z1[4], z1[5]);
        __half2 p6 = __floats2half2_rn(z0[6], z0[7]);
        __half2 p7 = __floats2half2_rn(z1[6], z1[7]);
        uint4 w0 = { h2u(p0), h2u(p1), h2u(p2), h2u(p3) };
        uint4 w1 = { h2u(p4), h2u(p5), h2u(p6), h2u(p7) };
        *(uint4*)dst = w0;
        *(uint4*)(dst + 8) = w1;
    }
}

// ================= edge FFN (1 thread/edge, [b][e][h] output) ===============
__global__ __launch_bounds__(256) void edge_ffn_kernel(
    const float* __restrict__ edge_attr,
    const float* __restrict__ e_w1, const float* __restrict__ e_b1,
    const float* __restrict__ e_w2, const float* __restrict__ e_b2)
{
    __shared__ float w1s[64], w2s[64], b1s[8], b2s[8];
    int tid = threadIdx.x;
    if (tid < 64) { w1s[tid] = e_w1[tid]; w2s[tid] = e_w2[tid]; }
    if (tid < 8)  { b1s[tid] = e_b1[tid]; b2s[tid] = e_b2[tid]; }
    __syncthreads();

    int gid = blockIdx.x * 256 + tid;   // < B*E
    float cur[8];
    const float* ap = edge_attr + (size_t)gid * Hn;
    #pragma unroll
    for (int i = 0; i < 8; ++i) cur[i] = ap[i];

    #pragma unroll
    for (int pass = 0; pass < 2; ++pass) {
        float t1[8], t2[8];
        #pragma unroll
        for (int j = 0; j < 8; ++j) {
            float s = b1s[j];
            #pragma unroll
            for (int i = 0; i < 8; ++i) s = fmaf(cur[i], w1s[i * 8 + j], s);
            t1[j] = fmaxf(s, 0.f);
        }
        #pragma unroll
        for (int j = 0; j < 8; ++j) {
            float s = b2s[j];
            #pragma unroll
            for (int i = 0; i < 8; ++i) s = fmaf(t1[i], w2s[i * 8 + j], s);
            t2[j] = s;
        }
        #pragma unroll
        for (int j = 0; j < 8; ++j) cur[j] = t2[j];
    }
    float* dst = g_ea + (size_t)gid * Hn;
    #pragma unroll
    for (int h = 0; h < 8; ++h) dst[h] = cur[h];
}

// ====== scatter: 1 thread per (edge, h) ======
__global__ __launch_bounds__(256) void edge_scatter_kernel(
    const int* __restrict__ edge_index)
{
    int gid = blockIdx.x * 256 + threadIdx.x;   // < B*E*8
    int h = gid & 7;
    int e = (gid >> 3) & (En - 1);
    int b = gid >> 19;

    int u = __ldg(edge_index + (size_t)b * 2 * En + e);
    int v = __ldg(edge_index + (size_t)b * 2 * En + En + e);
    float ea = g_ea[(size_t)(b * En + e) * Hn + h];

    size_t inoff = (size_t)(((u & 7) * 4 + ((v & 7) >> 1)) * 4 + ((u >> 3) & 1) * 2 + (v & 1));
    size_t a = ((((size_t)(b * 8 + h)) * 128 + (u >> 4)) * 256 + (v >> 3)) * 128 + inoff;
    g_bias[a] = __float2half_rn(__half2float(g_bias[a]) + ea);
}

// ================= tensor-core attention =================
__global__ __launch_bounds__(128) void attn_kernel(float* __restrict__ out)
{
    __shared__ __align__(16) __half sKh[2][64][40];
    __shared__ __align__(16) __half sKl[2][64][40];
    __shared__ __align__(16) __half sV [2][64][40];
    __shared__ __align__(16) __half sQh[64][40];
    __shared__ __align__(16) __half sQl[64][40];

    const int b = blockIdx.z, h = blockIdx.y;
    const int tid = threadIdx.x, warp = tid >> 5, lane = tid & 31;
    const int qb0 = blockIdx.x * 64;
    const int qbw = qb0 + warp * 16;

    const size_t plane = ((size_t)(b * Hn + h)) * Nn * DHn;
    const __half* gKh = g_Kh + plane;
    const __half* gKl = g_Kl + plane;
    const __half* gV  = g_Vh + plane;
    const __half* gB  = g_bias +
        ((((size_t)(b * Hn + h)) * 128 + (qbw >> 4)) * 256) * 128 + lane * 4;

    auto load_tile = [&](int buf, int t) {
        #pragma unroll
        for (int m = 0; m < 2; ++m) {
            int i = tid + m * 128;
            int row = i >> 2, c = (i & 3) * 8;
            const __half* s;
            s = gKh + (size_t)t * KT * DHn + row * DHn + c;
            CP_ASYNC16(sptr(&sKh[buf][row][c]), s);
            s = gKl + (size_t)t * KT * DHn + row * DHn + c;
            CP_ASYNC16(sptr(&sKl[buf][row][c]), s);
            s = gV + (size_t)t * KT * DHn + row * DHn + c;
            CP_ASYNC16(sptr(&sV[buf][row][c]), s);
        }
    };

    load_tile(0, 0);
    CP_COMMIT();

    {
        const __half* gqh = g_Qh + plane + (size_t)qb0 * DHn;
        const __half* gql = g_Ql + plane + (size_t)qb0 * DHn;
        for (int i = tid; i < 256; i += 128) {
            int row = i >> 2, c = (i & 3) * 8;
            *(uint4*)&sQh[row][c] = *(const uint4*)(gqh + row * DHn + c);
            *(uint4*)&sQl[row][c] = *(const uint4*)(gql + row * DHn + c);
        }
    }
    __syncthreads();

    u32 qh[2][4], ql[2][4];
    {
        int rowQ = warp * 16 + (lane & 7) + ((lane >> 3) & 1) * 8;
        int colQ = (lane >> 4) * 8;
        #pragma unroll
        for (int t = 0; t < 2; ++t) {
            LDSM4(qh[t], sptr(&sQh[rowQ][t * 16 + colQ]));
            LDSM4(ql[t], sptr(&sQl[rowQ][t * 16 + colQ]));
        }
    }

    const int rK = (lane & 7) + ((lane >> 4) & 1) * 8;
    const int cK = ((lane >> 3) & 1) * 8;
    const int rV = (lane & 7) + ((lane >> 3) & 1) * 8;
    const int cV = (lane >> 4) * 8;

    float O[4][4] = {};
    float mA = -INFINITY, mB = -INFINITY, lA = 0.f, lB = 0.f;

    for (int t = 0; t < NTILES; ++t) {
        if (t + 1 < NTILES) { load_tile((t + 1) & 1, t + 1); CP_COMMIT(); CP_WAIT1(); }
        else { CP_WAIT0(); }
        __syncthreads();
        const int buf = t & 1;

        float S[8][4];
        #pragma unroll
        for (int j = 0; j < 8; ++j)
            #pragma unroll
            for (int i = 0; i < 4; ++i) S[j][i] = 0.f;

        #pragma unroll
        for (int g = 0; g < 4; ++g) {
            u32 kh0[4], kh1[4], kl0[4], kl1[4];
            LDSM4(kh0, sptr(&sKh[buf][16 * g + rK][cK]));
            LDSM4(kh1, sptr(&sKh[buf][16 * g + rK][16 + cK]));
            LDSM4(kl0, sptr(&sKl[buf][16 * g + rK][cK]));
            LDSM4(kl1, sptr(&sKl[buf][16 * g + rK][16 + cK]));
            float* s0 = S[2 * g];
            float* s1 = S[2 * g + 1];
            MMA(s0, qh[0], kh0[0], kh0[1]); MMA(s0, qh[1], kh1[0], kh1[1]);
            MMA(s0, ql[0], kh0[0], kh0[1]); MMA(s0, ql[1], kh1[0], kh1[1]);
            MMA(s0, qh[0], kl0[0], kl0[1]); MMA(s0, qh[1], kl1[0], kl1[1]);
            MMA(s1, qh[0], kh0[2], kh0[3]); MMA(s1, qh[1], kh1[2], kh1[3]);
            MMA(s1, ql[0], kh0[2], kh0[3]); MMA(s1, ql[1], kh1[2], kh1[3]);
            MMA(s1, qh[0], kl0[2], kl0[3]); MMA(s1, qh[1], kl1[2], kl1[3]);
        }

        {
            const __half* bp = gB + (size_t)(t * 8) * 128;
            #pragma unroll
            for (int j = 0; j < 8; ++j) {
                uint2 u = *(const uint2*)(bp + (size_t)j * 128);
                __half2 hA, hB; memcpy(&hA, &u.x, 4); memcpy(&hB, &u.y, 4);
                float2 fa = __half22float2(hA);
                float2 fb = __half22float2(hB);
                S[j][0] += fa.x; S[j][1] += fa.y;
                S[j][2] += fb.x; S[j][3] += fb.y;
            }
        }

        float tmA = -INFINITY, tmB = -INFINITY;
        #pragma unroll
        for (int j = 0; j < 8; ++j) {
            tmA = fmaxf(tmA, fmaxf(S[j][0], S[j][1]));
            tmB = fmaxf(tmB, fmaxf(S[j][2], S[j][3]));
        }
        tmA = fmaxf(tmA, __shfl_xor_sync(0xffffffffu, tmA, 1));
        tmA = fmaxf(tmA, __shfl_xor_sync(0xffffffffu, tmA, 2));
        tmB = fmaxf(tmB, __shfl_xor_sync(0xffffffffu, tmB, 1));
        tmB = fmaxf(tmB, __shfl_xor_sync(0xffffffffu, tmB, 2));
        float mnA = fmaxf(mA, tmA), mnB = fmaxf(mB, tmB);
        float capA = __expf(mA - mnA), capB = __expf(mB - mnB);
        mA = mnA; mB = mnB;
        lA *= capA; lB *= capB;
        #pragma unroll
        for (int j = 0; j < 4; ++j) {
            O[j][0] *= capA; O[j][1] *= capA;
            O[j][2] *= capB; O[j][3] *= capB;
        }

        // ---- exp -> fp16 P fragments (single-term: fp16 rounding of P adds
        //      <= 2.4e-4 relative, inside the 1e-3 budget) ----
        u32 Ph[4][4];
        float sumA = 0.f, sumB = 0.f;
        #pragma unroll
        for (int j = 0; j < 8; ++j) {
            float p0 = __expf(S[j][0] - mA), p1 = __expf(S[j][1] - mA);
            float p2 = __expf(S[j][2] - mB), p3 = __expf(S[j][3] - mB);
            sumA += p0 + p1; sumB += p2 + p3;
            __half2 h01 = __floats2half2_rn(p0, p1);
            __half2 h23 = __floats2half2_rn(p2, p3);
            int g = j >> 1, ix = (j & 1) * 2;
            Ph[g][ix] = h2u(h01); Ph[g][ix + 1] = h2u(h23);
        }
        lA += sumA; lB += sumB;

        #pragma unroll
        for (int g = 0; g < 4; ++g) {
            u32 v0[4], v1[4];
            LDSM4T(v0, sptr(&sV[buf][16 * g + rV][cV]));
            LDSM4T(v1, sptr(&sV[buf][16 * g + rV][16 + cV]));
            MMA(O[0], Ph[g], v0[0], v0[1]); MMA(O[1], Ph[g], v0[2], v0[3]);
            MMA(O[2], Ph[g], v1[0], v1[1]); MMA(O[3], Ph[g], v1[2], v1[3]);
        }
        __syncthreads();
    }

    lA += __shfl_xor_sync(0xffffffffu, lA, 1);
    lA += __shfl_xor_sync(0xffffffffu, lA, 2);
    lB += __shfl_xor_sync(0xffffffffu, lB, 1);
    lB += __shfl_xor_sync(0xffffffffu, lB, 2);
    float iA = 1.f / lA, iB = 1.f / lB;
    int rA = qbw + (lane >> 2), rB = rA + 8;
    int cb = h * DHn + 2 * (lane & 3);
    #pragma unroll
    for (int j = 0; j < 4; ++j) {
        float2 oa = { O[j][0] * iA, O[j][1] * iA };
        float2 ob = { O[j][2] * iB, O[j][3] * iB };
        *(float2*)&out[(size_t)(b * Nn + rA) * On + cb + 8 * j] = oa;
        *(float2*)&out[(size_t)(b * Nn + rB) * On + cb + 8 * j] = ob;
    }
}

// ================= launch =================
extern "C" void kernel_launch(void* const* d_in, const int* in_sizes, int n_in,
                              void* d_out, int out_size)
{
    const float* x         = (const float*)d_in[0];
    const float* adj       = (const float*)d_in[1];
    const float* edge_attr = (const float*)d_in[2];
    const float* qkv_w     = (const float*)d_in[3];
    const float* qkv_b     = (const float*)d_in[4];
    const float* e_w1      = (const float*)d_in[5];
    const float* e_b1      = (const float*)d_in[6];
    const float* e_w2      = (const float*)d_in[7];
    const float* e_b2      = (const float*)d_in[8];
    const float* shifts    = (const float*)d_in[9];
    const float* widths    = (const float*)d_in[10];
    const float* slW       = (const float*)d_in[11];
    const int*   edge_idx  = (const int*)d_in[12];
    float*       out       = (float*)d_out;

    edge_ffn_kernel<<<(Bn * En) / 256, 256>>>(edge_attr, e_w1, e_b1, e_w2, e_b2);
    bias_kernel<<<(Bn * 128 * 256 * 8) / 256, 256>>>(adj, shifts, widths, slW);
    convert_kernel<<<(Bn * Nn * DINn + DINn * 768 + 255) / 256, 256>>>(x, qkv_w);
    qkv_mma_kernel<<<dim3(768 / 128, (Bn * Nn) / 64), 128>>>(qkv_b);
    edge_scatter_kernel<<<(Bn * En * Hn) / 256, 256>>>(edge_idx);
    attn_kernel<<<dim3(Nn / 64, Hn, Bn), 128>>>(out);
}

// round 16
// speedup vs baseline: 3.5534x; 1.0383x over previous
#include <cuda_runtime.h>
#include <cuda_fp16.h>
#include <math.h>
#include <stdint.h>

#define Bn   2
#define Nn   2048
#define Hn   8
#define DHn  32
#define En   65536
#define DINn 256
#define On   256
#define INVSCALE 0.17677669529663687f
#define LOGCLIP  -13.815510557964274f

#define KT 64
#define NTILES (Nn / KT)

typedef uint32_t u32;

// -------- static device scratch --------
__device__ __half g_Qh[(size_t)Bn * Hn * Nn * DHn];
__device__ __half g_Ql[(size_t)Bn * Hn * Nn * DHn];
__device__ __half g_Kh[(size_t)Bn * Hn * Nn * DHn];
__device__ __half g_Kl[(size_t)Bn * Hn * Nn * DHn];
__device__ __half g_Vh[(size_t)Bn * Hn * Nn * DHn];
__device__ float  g_ea[(size_t)Bn * En * Hn];   // [b][e][h] (coalesced for scatter)
// fragment-interleaved bias: [b][h][q>>4][k>>3][lane 0..31][4 halfs]
__device__ __half g_bias[(size_t)Bn * Hn * Nn * Nn];
// split-fp16 x, fp16 w (w low bits dropped: error ~1.4e-4 rms, inside budget)
__device__ __half g_xh[(size_t)Bn * Nn * DINn];
__device__ __half g_xl[(size_t)Bn * Nn * DINn];
__device__ __half g_wh[(size_t)DINn * 768];

#define CP_ASYNC16(smem_u32, gptr) \
    asm volatile("cp.async.cg.shared.global [%0], [%1], 16;" :: "r"(smem_u32), "l"(gptr))
#define CP_COMMIT() asm volatile("cp.async.commit_group;")
#define CP_WAIT1()  asm volatile("cp.async.wait_group 1;")
#define CP_WAIT0()  asm volatile("cp.async.wait_group 0;")

__device__ __forceinline__ u32 sptr(const void* p) {
    return (u32)__cvta_generic_to_shared(p);
}
#define LDSM4(r, addr) \
    asm volatile("ldmatrix.sync.aligned.m8n8.x4.shared.b16 {%0,%1,%2,%3}, [%4];" \
        : "=r"(r[0]), "=r"(r[1]), "=r"(r[2]), "=r"(r[3]) : "r"(addr))
#define LDSM4T(r, addr) \
    asm volatile("ldmatrix.sync.aligned.m8n8.x4.trans.shared.b16 {%0,%1,%2,%3}, [%4];" \
        : "=r"(r[0]), "=r"(r[1]), "=r"(r[2]), "=r"(r[3]) : "r"(addr))
#define MMA(c, a, b0, b1) \
    asm volatile("mma.sync.aligned.m16n8k16.row.col.f32.f16.f16.f32 " \
        "{%0,%1,%2,%3},{%4,%5,%6,%7},{%8,%9},{%0,%1,%2,%3};" \
        : "+f"(c[0]), "+f"(c[1]), "+f"(c[2]), "+f"(c[3]) \
        : "r"(a[0]), "r"(a[1]), "r"(a[2]), "r"(a[3]), "r"(b0), "r"(b1))

__device__ __forceinline__ u32 h2u(__half2 h) { u32 r; memcpy(&r, &h, 4); return r; }

// ================= fp32 -> fp16 conversion (x split, w single) =============
__global__ __launch_bounds__(256) void convert_kernel(
    const float* __restrict__ x, const float* __restrict__ w)
{
    int i = blockIdx.x * 256 + threadIdx.x;
    const int NX = Bn * Nn * DINn;          // 1048576
    if (i < NX) {
        float v = x[i];
        __half hi = __float2half_rn(v);
        g_xh[i] = hi;
        g_xl[i] = __float2half_rn(v - __half2float(hi));
    } else {
        int j = i - NX;
        if (j < DINn * 768) {
            g_wh[j] = __float2half_rn(w[j]);
        }
    }
}

// ================= QKV projection: 2-term split-fp16 tensor-core GEMM =======
// C = (xh + xl) @ wh; tile M=64, N=128 per CTA (128 thr), grid 6x64.
#define QK_PADX 40
#define QK_PADW 136
__global__ __launch_bounds__(128, 3) void qkv_mma_kernel(const float* __restrict__ bias)
{
    __shared__ __align__(16) __half sXh[2][64][QK_PADX];
    __shared__ __align__(16) __half sXl[2][64][QK_PADX];
    __shared__ __align__(16) __half sWh[2][32][QK_PADW];

    const int tid = threadIdx.x, warp = tid >> 5, lane = tid & 31;
    const int row0 = blockIdx.y * 64;
    const int col0 = blockIdx.x * 128;

    auto load_tile = [&](int buf, int k0) {
        // X: 64 rows x 32 halfs (hi+lo): 256 16B-chunks each
        #pragma unroll
        for (int m = 0; m < 2; ++m) {
            int i = tid + m * 128;
            int r = i >> 2, c = (i & 3) * 8;
            const __half* s = g_xh + (size_t)(row0 + r) * DINn + k0 + c;
            CP_ASYNC16(sptr(&sXh[buf][r][c]), s);
            s = g_xl + (size_t)(row0 + r) * DINn + k0 + c;
            CP_ASYNC16(sptr(&sXl[buf][r][c]), s);
        }
        // W: 32 rows x 128 halfs: 512 16B-chunks
        #pragma unroll
        for (int m = 0; m < 4; ++m) {
            int i = tid + m * 128;
            int r = i >> 4, c = (i & 15) * 8;
            const __half* s = g_wh + (size_t)(k0 + r) * 768 + col0 + c;
            CP_ASYNC16(sptr(&sWh[buf][r][c]), s);
        }
    };

    load_tile(0, 0);
    CP_COMMIT();

    float C[16][4];
    #pragma unroll
    for (int j = 0; j < 16; ++j)
        #pragma unroll
        for (int i = 0; i < 4; ++i) C[j][i] = 0.f;

    const int rA = warp * 16 + (lane & 15);
    const int cA = (lane >> 4) * 8;
    const int rB = (lane & 7) + ((lane >> 3) & 1) * 8;
    const int cB = (lane >> 4) * 8;

    for (int kc = 0; kc < 8; ++kc) {
        if (kc + 1 < 8) { load_tile((kc + 1) & 1, (kc + 1) * 32); CP_COMMIT(); CP_WAIT1(); }
        else { CP_WAIT0(); }
        __syncthreads();
        const int buf = kc & 1;

        #pragma unroll
        for (int ks = 0; ks < 2; ++ks) {
            const int ko = ks * 16;
            u32 ah[4], al[4];
            LDSM4(ah, sptr(&sXh[buf][rA][ko + cA]));
            LDSM4(al, sptr(&sXl[buf][rA][ko + cA]));
            #pragma unroll
            for (int g = 0; g < 8; ++g) {
                u32 wh[4];
                LDSM4T(wh, sptr(&sWh[buf][ko + rB][g * 16 + cB]));
                MMA(C[2 * g],     ah, wh[0], wh[1]);
                MMA(C[2 * g + 1], ah, wh[2], wh[3]);
                MMA(C[2 * g],     al, wh[0], wh[1]);
                MMA(C[2 * g + 1], al, wh[2], wh[3]);
            }
        }
        __syncthreads();
    }

    #pragma unroll
    for (int j = 0; j < 16; ++j) {
        #pragma unroll
        for (int i = 0; i < 4; ++i) {
            int row = row0 + warp * 16 + (lane >> 2) + (i >> 1) * 8;
            int col = col0 + j * 8 + 2 * (lane & 3) + (i & 1);
            float v = C[j][i] + __ldg(bias + col);
            int bb = row >> 11, n = row & (Nn - 1);
            int s = col >> 8, hh = (col >> 5) & 7, d = col & 31;
            size_t idx = (((size_t)(bb * Hn + hh)) * Nn + n) * DHn + d;
            if (s == 0) {
                float vq = v * INVSCALE;
                __half hi = __float2half_rn(vq);
                g_Qh[idx] = hi;
                g_Ql[idx] = __float2half_rn(vq - __half2float(hi));
            } else if (s == 1) {
                __half hi = __float2half_rn(v);
                g_Kh[idx] = hi;
                g_Kl[idx] = __float2half_rn(v - __half2float(hi));
            } else {
                g_Vh[idx] = __float2half_rn(v);
            }
        }
    }
}

// ====== dense bias (moire + self-loop), coalesced 32B stores ======
__global__ __launch_bounds__(256) void bias_kernel(
    const float* __restrict__ adj,
    const float* __restrict__ shifts, const float* __restrict__ widths,
    const float* __restrict__ slW)
{
    int idx = blockIdx.x * 256 + threadIdx.x;   // B * 128 * 256 * 8 = 524288
    int qlow = idx & 7;
    int k8   = (idx >> 3) & 255;
    int qblk = (idx >> 11) & 127;
    int b    = idx >> 18;

    int q0 = qblk * 16 + qlow;
    int q1 = q0 + 8;
    int kbase = k8 * 8;

    const float* ap0 = adj + ((size_t)b * Nn + q0) * Nn + kbase;
    const float* ap1 = adj + ((size_t)b * Nn + q1) * Nn + kbase;
    float4 x0 = *(const float4*)ap0, x1 = *(const float4*)(ap0 + 4);
    float4 y0 = *(const float4*)ap1, y1 = *(const float4*)(ap1 + 4);
    float a0[8] = {x0.x, x0.y, x0.z, x0.w, x1.x, x1.y, x1.z, x1.w};
    float a1[8] = {y0.x, y0.y, y0.z, y0.w, y1.x, y1.y, y1.z, y1.w};
    int d0 = q0 - kbase;
    int d1 = q1 - kbase;

    #pragma unroll
    for (int h = 0; h < 8; ++h) {
        float sh = __ldg(shifts + h);
        float wd = __ldg(widths + h);
        float inv2w2 = 1.f / (2.f * wd * wd);
        float sl = __ldg(slW + h);

        float z0[8], z1[8];
        #pragma unroll
        for (int i = 0; i < 8; ++i) {
            float t0 = a0[i] - sh;
            float t1 = a1[i] - sh;
            z0[i] = fmaxf(-t0 * t0 * inv2w2, LOGCLIP);
            z1[i] = fmaxf(-t1 * t1 * inv2w2, LOGCLIP);
            if (i == d0) z0[i] += sl;
            if (i == d1) z1[i] += sl;
        }
        __half* dst = g_bias +
            ((((size_t)(b * 8 + h)) * 128 + qblk) * 256 + k8) * 128 + qlow * 16;
        __half2 p0 = __floats2half2_rn(z0[0], z0[1]);
        __half2 p1 = __floats2half2_rn(z1[0], z1[1]);
        __half2 p2 = __floats2half2_rn(z0[2], z0[3]);
        __half2 p3 = __floats2half2_rn(z1[2], z1[3]);
        __half2 p4 = __floats2half2_rn(z0[4], z0[5]);
        __half2 p5 = __floats2half2_rn(z1[4], z1[5]);
        __half2 p6 = __floats2half2_rn(z0[6], z0[7]);
        __half2 p7 = __floats2half2_rn(z1[6], z1[7]);
        uint4 w0 = { h2u(p0), h2u(p1), h2u(p2), h2u(p3) };
        uint4 w1 = { h2u(p4), h2u(p5), h2u(p6), h2u(p7) };
        *(uint4*)dst = w0;
        *(uint4*)(dst + 8) = w1;
    }
}

// ================= edge FFN (1 thread/edge, [b][e][h] output) ===============
__global__ __launch_bounds__(256) void edge_ffn_kernel(
    const float* __restrict__ edge_attr,
    const float* __restrict__ e_w1, const float* __restrict__ e_b1,
    const float* __restrict__ e_w2, const float* __restrict__ e_b2)
{
    __shared__ float w1s[64], w2s[64], b1s[8], b2s[8];
    int tid = threadIdx.x;
    if (tid < 64) { w1s[tid] = e_w1[tid]; w2s[tid] = e_w2[tid]; }
    if (tid < 8)  { b1s[tid] = e_b1[tid]; b2s[tid] = e_b2[tid]; }
    __syncthreads();

    int gid = blockIdx.x * 256 + tid;   // < B*E
    float cur[8];
    const float* ap = edge_attr + (size_t)gid * Hn;
    #pragma unroll
    for (int i = 0; i < 8; ++i) cur[i] = ap[i];

    #pragma unroll
    for (int pass = 0; pass < 2; ++pass) {
        float t1[8], t2[8];
        #pragma unroll
        for (int j = 0; j < 8; ++j) {
            float s = b1s[j];
            #pragma unroll
            for (int i = 0; i < 8; ++i) s = fmaf(cur[i], w1s[i * 8 + j], s);
            t1[j] = fmaxf(s, 0.f);
        }
        #pragma unroll
        for (int j = 0; j < 8; ++j) {
            float s = b2s[j];
            #pragma unroll
            for (int i = 0; i < 8; ++i) s = fmaf(t1[i], w2s[i * 8 + j], s);
            t2[j] = s;
        }
        #pragma unroll
        for (int j = 0; j < 8; ++j) cur[j] = t2[j];
    }
    float* dst = g_ea + (size_t)gid * Hn;
    #pragma unroll
    for (int h = 0; h < 8; ++h) dst[h] = cur[h];
}

// ====== scatter: 1 thread per (edge, h) ======
__global__ __launch_bounds__(256) void edge_scatter_kernel(
    const int* __restrict__ edge_index)
{
    int gid = blockIdx.x * 256 + threadIdx.x;   // < B*E*8
    int h = gid & 7;
    int e = (gid >> 3) & (En - 1);
    int b = gid >> 19;

    int u = __ldg(edge_index + (size_t)b * 2 * En + e);
    int v = __ldg(edge_index + (size_t)b * 2 * En + En + e);
    float ea = g_ea[(size_t)(b * En + e) * Hn + h];

    size_t inoff = (size_t)(((u & 7) * 4 + ((v & 7) >> 1)) * 4 + ((u >> 3) & 1) * 2 + (v & 1));
    size_t a = ((((size_t)(b * 8 + h)) * 128 + (u >> 4)) * 256 + (v >> 3)) * 128 + inoff;
    g_bias[a] = __float2half_rn(__half2float(g_bias[a]) + ea);
}

// ================= tensor-core attention =================
__global__ __launch_bounds__(128) void attn_kernel(float* __restrict__ out)
{
    __shared__ __align__(16) __half sKh[2][64][40];
    __shared__ __align__(16) __half sKl[2][64][40];
    __shared__ __align__(16) __half sV [2][64][40];
    __shared__ __align__(16) __half sQh[64][40];
    __shared__ __align__(16) __half sQl[64][40];

    const int b = blockIdx.z, h = blockIdx.y;
    const int tid = threadIdx.x, warp = tid >> 5, lane = tid & 31;
    const int qb0 = blockIdx.x * 64;
    const int qbw = qb0 + warp * 16;

    const size_t plane = ((size_t)(b * Hn + h)) * Nn * DHn;
    const __half* gKh = g_Kh + plane;
    const __half* gKl = g_Kl + plane;
    const __half* gV  = g_Vh + plane;
    const __half* gB  = g_bias +
        ((((size_t)(b * Hn + h)) * 128 + (qbw >> 4)) * 256) * 128 + lane * 4;

    auto load_tile = [&](int buf, int t) {
        #pragma unroll
        for (int m = 0; m < 2; ++m) {
            int i = tid + m * 128;
            int row = i >> 2, c = (i & 3) * 8;
            const __half* s;
            s = gKh + (size_t)t * KT * DHn + row * DHn + c;
            CP_ASYNC16(sptr(&sKh[buf][row][c]), s);
            s = gKl + (size_t)t * KT * DHn + row * DHn + c;
            CP_ASYNC16(sptr(&sKl[buf][row][c]), s);
            s = gV + (size_t)t * KT * DHn + row * DHn + c;
            CP_ASYNC16(sptr(&sV[buf][row][c]), s);
        }
    };

    load_tile(0, 0);
    CP_COMMIT();

    {
        const __half* gqh = g_Qh + plane + (size_t)qb0 * DHn;
        const __half* gql = g_Ql + plane + (size_t)qb0 * DHn;
        for (int i = tid; i < 256; i += 128) {
            int row = i >> 2, c = (i & 3) * 8;
            *(uint4*)&sQh[row][c] = *(const uint4*)(gqh + row * DHn + c);
            *(uint4*)&sQl[row][c] = *(const uint4*)(gql + row * DHn + c);
        }
    }
    __syncthreads();

    u32 qh[2][4], ql[2][4];
    {
        int rowQ = warp * 16 + (lane & 7) + ((lane >> 3) & 1) * 8;
        int colQ = (lane >> 4) * 8;
        #pragma unroll
        for (int t = 0; t < 2; ++t) {
            LDSM4(qh[t], sptr(&sQh[rowQ][t * 16 + colQ]));
            LDSM4(ql[t], sptr(&sQl[rowQ][t * 16 + colQ]));
        }
    }

    const int rK = (lane & 7) + ((lane >> 4) & 1) * 8;
    const int cK = ((lane >> 3) & 1) * 8;
    const int rV = (lane & 7) + ((lane >> 3) & 1) * 8;
    const int cV = (lane >> 4) * 8;

    float O[4][4] = {};
    float mA = -INFINITY, mB = -INFINITY, lA = 0.f, lB = 0.f;

    for (int t = 0; t < NTILES; ++t) {
        if (t + 1 < NTILES) { load_tile((t + 1) & 1, t + 1); CP_COMMIT(); CP_WAIT1(); }
        else { CP_WAIT0(); }
        __syncthreads();
        const int buf = t & 1;

        float S[8][4];
        #pragma unroll
        for (int j = 0; j < 8; ++j)
            #pragma unroll
            for (int i = 0; i < 4; ++i) S[j][i] = 0.f;

        #pragma unroll
        for (int g = 0; g < 4; ++g) {
            u32 kh0[4], kh1[4], kl0[4], kl1[4];
            LDSM4(kh0, sptr(&sKh[buf][16 * g + rK][cK]));
            LDSM4(kh1, sptr(&sKh[buf][16 * g + rK][16 + cK]));
            LDSM4(kl0, sptr(&sKl[buf][16 * g + rK][cK]));
            LDSM4(kl1, sptr(&sKl[buf][16 * g + rK][16 + cK]));
            float* s0 = S[2 * g];
            float* s1 = S[2 * g + 1];
            MMA(s0, qh[0], kh0[0], kh0[1]); MMA(s0, qh[1], kh1[0], kh1[1]);
            MMA(s0, ql[0], kh0[0], kh0[1]); MMA(s0, ql[1], kh1[0], kh1[1]);
            MMA(s0, qh[0], kl0[0], kl0[1]); MMA(s0, qh[1], kl1[0], kl1[1]);
            MMA(s1, qh[0], kh0[2], kh0[3]); MMA(s1, qh[1], kh1[2], kh1[3]);
            MMA(s1, ql[0], kh0[2], kh0[3]); MMA(s1, ql[1], kh1[2], kh1[3]);
            MMA(s1, qh[0], kl0[2], kl0[3]); MMA(s1, qh[1], kl1[2], kl1[3]);
        }

        {
            const __half* bp = gB + (size_t)(t * 8) * 128;
            #pragma unroll
            for (int j = 0; j < 8; ++j) {
                uint2 u = *(const uint2*)(bp + (size_t)j * 128);
                __half2 hA, hB; memcpy(&hA, &u.x, 4); memcpy(&hB, &u.y, 4);
                float2 fa = __half22float2(hA);
                float2 fb = __half22float2(hB);
                S[j][0] += fa.x; S[j][1] += fa.y;
                S[j][2] += fb.x; S[j][3] += fb.y;
            }
        }

        float tmA = -INFINITY, tmB = -INFINITY;
        #pragma unroll
        for (int j = 0; j < 8; ++j) {
            tmA = fmaxf(tmA, fmaxf(S[j][0], S[j][1]));
            tmB = fmaxf(tmB, fmaxf(S[j][2], S[j][3]));
        }
        tmA = fmaxf(tmA, __shfl_xor_sync(0xffffffffu, tmA, 1));
        tmA = fmaxf(tmA, __shfl_xor_sync(0xffffffffu, tmA, 2));
        tmB = fmaxf(tmB, __shfl_xor_sync(0xffffffffu, tmB, 1));
        tmB = fmaxf(tmB, __shfl_xor_sync(0xffffffffu, tmB, 2));
        float mnA = fmaxf(mA, tmA), mnB = fmaxf(mB, tmB);
        float capA = __expf(mA - mnA), capB = __expf(mB - mnB);
        mA = mnA; mB = mnB;
        lA *= capA; lB *= capB;
        #pragma unroll
        for (int j = 0; j < 4; ++j) {
            O[j][0] *= capA; O[j][1] *= capA;
            O[j][2] *= capB; O[j][3] *= capB;
        }

        u32 Ph[4][4];
        float sumA = 0.f, sumB = 0.f;
        #pragma unroll
        for (int j = 0; j < 8; ++j) {
            float p0 = __expf(S[j][0] - mA), p1 = __expf(S[j][1] - mA);
            float p2 = __expf(S[j][2] - mB), p3 = __expf(S[j][3] - mB);
            sumA += p0 + p1; sumB += p2 + p3;
            __half2 h01 = __floats2half2_rn(p0, p1);
            __half2 h23 = __floats2half2_rn(p2, p3);
            int g = j >> 1, ix = (j & 1) * 2;
            Ph[g][ix] = h2u(h01); Ph[g][ix + 1] = h2u(h23);
        }
        lA += sumA; lB += sumB;

        #pragma unroll
        for (int g = 0; g < 4; ++g) {
            u32 v0[4], v1[4];
            LDSM4T(v0, sptr(&sV[buf][16 * g + rV][cV]));
            LDSM4T(v1, sptr(&sV[buf][16 * g + rV][16 + cV]));
            MMA(O[0], Ph[g], v0[0], v0[1]); MMA(O[1], Ph[g], v0[2], v0[3]);
            MMA(O[2], Ph[g], v1[0], v1[1]); MMA(O[3], Ph[g], v1[2], v1[3]);
        }
        __syncthreads();
    }

    lA += __shfl_xor_sync(0xffffffffu, lA, 1);
    lA += __shfl_xor_sync(0xffffffffu, lA, 2);
    lB += __shfl_xor_sync(0xffffffffu, lB, 1);
    lB += __shfl_xor_sync(0xffffffffu, lB, 2);
    float iA = 1.f / lA, iB = 1.f / lB;
    int rA = qbw + (lane >> 2), rB = rA + 8;
    int cb = h * DHn + 2 * (lane & 3);
    #pragma unroll
    for (int j = 0; j < 4; ++j) {
        float2 oa = { O[j][0] * iA, O[j][1] * iA };
        float2 ob = { O[j][2] * iB, O[j][3] * iB };
        *(float2*)&out[(size_t)(b * Nn + rA) * On + cb + 8 * j] = oa;
        *(float2*)&out[(size_t)(b * Nn + rB) * On + cb + 8 * j] = ob;
    }
}

// ================= launch =================
extern "C" void kernel_launch(void* const* d_in, const int* in_sizes, int n_in,
                              void* d_out, int out_size)
{
    const float* x         = (const float*)d_in[0];
    const float* adj       = (const float*)d_in[1];
    const float* edge_attr = (const float*)d_in[2];
    const float* qkv_w     = (const float*)d_in[3];
    const float* qkv_b     = (const float*)d_in[4];
    const float* e_w1      = (const float*)d_in[5];
    const float* e_b1      = (const float*)d_in[6];
    const float* e_w2      = (const float*)d_in[7];
    const float* e_b2      = (const float*)d_in[8];
    const float* shifts    = (const float*)d_in[9];
    const float* widths    = (const float*)d_in[10];
    const float* slW       = (const float*)d_in[11];
    const int*   edge_idx  = (const int*)d_in[12];
    float*       out       = (float*)d_out;

    edge_ffn_kernel<<<(Bn * En) / 256, 256>>>(edge_attr, e_w1, e_b1, e_w2, e_b2);
    bias_kernel<<<(Bn * 128 * 256 * 8) / 256, 256>>>(adj, shifts, widths, slW);
    convert_kernel<<<(Bn * Nn * DINn + DINn * 768 + 255) / 256, 256>>>(x, qkv_w);
    qkv_mma_kernel<<<dim3(768 / 128, (Bn * Nn) / 64), 128>>>(qkv_b);
    edge_scatter_kernel<<<(Bn * En * Hn) / 256, 256>>>(edge_idx);
    attn_kernel<<<dim3(Nn / 64, Hn, Bn), 128>>>(out);
}